// round 3
// baseline (speedup 1.0000x reference)
#include <cuda_runtime.h>

#define BB 8
#define NN 8192
#define MM 2048
#define CC 64
#define KK 64
#define R2 0.01f
#define ROWSTRIDE 72   // floats per point row: [x,y,z,pad, f0..f63, 4 pad]

// Scratch (no cudaMalloc allowed): 18.9MB transposed points + 4MB indices
__device__ float g_ptsT[BB * NN * ROWSTRIDE];
__device__ int   g_idx[BB * MM * KK];

// ---------------------------------------------------------------------------
// Kernel A: transpose feature [B][C][N] + xyz [B][3][N] into point-major rows
//   g_ptsT[b][n][0..2] = xyz, g_ptsT[b][n][4+c] = feature[b][c][n]
// ---------------------------------------------------------------------------
__global__ void __launch_bounds__(256) transpose_kernel(
    const float* __restrict__ xyz, const float* __restrict__ feat)
{
    __shared__ float s[64][65];     // padded: conflict-free transposed reads
    const int b  = blockIdx.y;
    const int n0 = blockIdx.x * 64;
    const int tid = threadIdx.x;
    const int p  = tid & 63;
    const int c0 = tid >> 6;        // 0..3

    // coalesced channel-major loads
    #pragma unroll
    for (int cc = 0; cc < 64; cc += 4) {
        const int c = cc + c0;
        s[c][p] = feat[((size_t)(b * 64 + c)) * NN + n0 + p];
    }
    __syncthreads();

    // coalesced point-major writes (warp writes 32 consecutive channels)
    #pragma unroll
    for (int it = 0; it < 16; ++it) {
        const int o  = it * 256 + tid;
        const int pp = o >> 6;
        const int c  = o & 63;
        g_ptsT[((size_t)(b * NN + n0 + pp)) * ROWSTRIDE + 4 + c] = s[c][pp];
    }

    // xyz columns (small)
    if (tid < 192) {
        const int c  = tid >> 6;
        const int pp = tid & 63;
        g_ptsT[((size_t)(b * NN + n0 + pp)) * ROWSTRIDE + c] =
            xyz[((size_t)(b * 3 + c)) * NN + n0 + pp];
    }
}

// ---------------------------------------------------------------------------
// Kernel B: ball query. One warp per query, xyz tiled through shared memory.
// d2 replicates reference bit-exactly (hypothesis):
//   norms:  ((x*x + y*y) + z*z), rn mul / rn add  (XLA pointwise+reduce)
//   dot:    sequential fp32 FMA chain over k=0,1,2 (cuBLAS/Eigen K=3 GEMM)
//   d2:     (sq + sp) - 2*dot, rn ops, no contraction
// ---------------------------------------------------------------------------
__global__ void __launch_bounds__(512) ballquery_kernel(
    const float* __restrict__ new_xyz, const float* __restrict__ xyz)
{
    __shared__ float sx[2048], sy[2048], sz[2048];
    const int b    = blockIdx.y;
    const int warp = threadIdx.x >> 5;
    const int lane = threadIdx.x & 31;
    const int m    = blockIdx.x * 16 + warp;
    const int q    = b * MM + m;

    const float qx = new_xyz[(b * 3 + 0) * MM + m];
    const float qy = new_xyz[(b * 3 + 1) * MM + m];
    const float qz = new_xyz[(b * 3 + 2) * MM + m];
    const float sq = __fadd_rn(__fadd_rn(__fmul_rn(qx, qx), __fmul_rn(qy, qy)),
                               __fmul_rn(qz, qz));

    int cnt = 0;
    int first = 0;
    const unsigned lt_mask = (lane == 0) ? 0u : (0xffffffffu >> (32 - lane));

    for (int t = 0; t < NN; t += 2048) {
        // cooperative tile load (coalesced)
        for (int i = threadIdx.x; i < 2048; i += 512) {
            sx[i] = xyz[(b * 3 + 0) * NN + t + i];
            sy[i] = xyz[(b * 3 + 1) * NN + t + i];
            sz[i] = xyz[(b * 3 + 2) * NN + t + i];
        }
        __syncthreads();

        if (cnt < 64) {
            for (int c = 0; c < 2048; c += 32) {
                const float px = sx[c + lane];
                const float py = sy[c + lane];
                const float pz = sz[c + lane];
                // |p|^2 full fp32, mul/add
                const float sp = __fadd_rn(__fadd_rn(__fmul_rn(px, px), __fmul_rn(py, py)),
                                           __fmul_rn(pz, pz));
                // fp32 GEMM dot: acc=0; acc=fma(q_k,p_k,acc), k=0,1,2
                float dt = __fmul_rn(qx, px);          // fma(q0,p0,0) == rn mul
                dt = __fmaf_rn(qy, py, dt);
                dt = __fmaf_rn(qz, pz, dt);
                const float d2 = __fsub_rn(__fadd_rn(sq, sp), __fmul_rn(2.0f, dt));
                const bool  in = d2 < R2;
                const unsigned mask = __ballot_sync(0xffffffffu, in);
                if (mask) {
                    const int n = t + c + lane;
                    if (cnt == 0)
                        first = __shfl_sync(0xffffffffu, n, __ffs(mask) - 1);
                    if (in) {
                        const int pos = cnt + __popc(mask & lt_mask);
                        if (pos < 64) g_idx[q * 64 + pos] = n;
                    }
                    cnt += __popc(mask);
                    if (cnt >= 64) break;
                }
            }
        }
        __syncthreads();
    }

    // pad remaining slots with first in-range index (0 if none)
    for (int p = cnt + lane; p < 64; p += 32)
        g_idx[q * 64 + p] = first;
}

// ---------------------------------------------------------------------------
// Kernel C: gather + concat. One block per (b, m).
// Stage 64 neighbor rows (288B contiguous each) in smem, write coalesced.
// ---------------------------------------------------------------------------
__global__ void __launch_bounds__(256) gather_kernel(
    const float* __restrict__ new_xyz, float* __restrict__ out)
{
    __shared__ int   sidx[64];
    __shared__ float srow[64][73];   // stride 73: conflict-free column reads
    const int b   = blockIdx.y;
    const int m   = blockIdx.x;
    const int tid = threadIdx.x;
    const int q   = b * MM + m;

    if (tid < 64) sidx[tid] = g_idx[q * 64 + tid];
    __syncthreads();

    // stage neighbor rows (contiguous 288B chunks, L2-resident ptsT)
    for (int f = tid; f < 64 * ROWSTRIDE; f += 256) {
        const int r   = f / ROWSTRIDE;
        const int col = f - r * ROWSTRIDE;
        srow[r][col] = g_ptsT[((size_t)(b * NN + sidx[r])) * ROWSTRIDE + col];
    }
    __syncthreads();

    // write all 67*64 outputs, fully coalesced in k
    for (int o = tid; o < 67 * 64; o += 256) {
        const int c = o >> 6;
        const int k = o & 63;
        float v;
        if (c < 3) v = srow[k][c] - new_xyz[(b * 3 + c) * MM + m];
        else       v = srow[k][c + 1];
        out[(((size_t)b * 67 + c) * MM + m) * 64 + k] = v;
    }
}

// ---------------------------------------------------------------------------
extern "C" void kernel_launch(void* const* d_in, const int* in_sizes, int n_in,
                              void* d_out, int out_size)
{
    const float* new_xyz = (const float*)d_in[0];  // (8, 3, 2048)
    const float* xyz     = (const float*)d_in[1];  // (8, 3, 8192)
    const float* feature = (const float*)d_in[2];  // (8, 64, 8192)
    float* out = (float*)d_out;                    // (8, 67, 2048, 64)

    transpose_kernel<<<dim3(NN / 64, BB), 256>>>(xyz, feature);
    ballquery_kernel<<<dim3(MM / 16, BB), 512>>>(new_xyz, xyz);
    gather_kernel<<<dim3(MM, BB), 256>>>(new_xyz, out);
}

// round 4
// speedup vs baseline: 1.5147x; 1.5147x over previous
#include <cuda_runtime.h>
#include <limits.h>

#define BB 8
#define NN 8192
#define MM 2048
#define CC 64
#define KK 64
#define R2 0.01f
#define ROWSTRIDE 72       // floats per point row: [x,y,z,pad, f0..f63, 4 pad]
#define NCELL 1000         // 10x10x10 grid, cell size 0.1
#define RREACH 0.1002f     // conservative cell reach (covers d2 rounding slack)
#define HCAP 128           // per-query candidate-hit cap (max expected ~75)

// Scratch (no cudaMalloc allowed)
__device__ float  g_ptsT[BB * NN * ROWSTRIDE];   // 18.9MB transposed points
__device__ int    g_idx[BB * MM * KK];           // 4MB neighbor indices
__device__ int    g_cellcnt[BB * NCELL];
__device__ int    g_cellstart[BB * (NCELL + 1)];
__device__ int    g_cellofs[BB * NCELL];
__device__ float4 g_cellpts[BB * NN];            // (x,y,z, idx-bits) cell-sorted

__device__ __forceinline__ int cell_of(float x, float y, float z)
{
    int cx = (int)(x * 10.0f); cx = min(max(cx, 0), 9);
    int cy = (int)(y * 10.0f); cy = min(max(cy, 0), 9);
    int cz = (int)(z * 10.0f); cz = min(max(cz, 0), 9);
    return (cx * 10 + cy) * 10 + cz;
}

// ---------------------------------------------------------------------------
// Cell-grid build: zero -> histogram -> scan -> scatter
// ---------------------------------------------------------------------------
__global__ void zero_kernel()
{
    const int b = blockIdx.x;
    if (threadIdx.x < NCELL) g_cellcnt[b * NCELL + threadIdx.x] = 0;
}

__global__ void hist_kernel(const float* __restrict__ xyz)
{
    const int b = blockIdx.y;
    const int n = blockIdx.x * 256 + threadIdx.x;
    const float x = xyz[(b * 3 + 0) * NN + n];
    const float y = xyz[(b * 3 + 1) * NN + n];
    const float z = xyz[(b * 3 + 2) * NN + n];
    atomicAdd(&g_cellcnt[b * NCELL + cell_of(x, y, z)], 1);
}

__global__ void __launch_bounds__(1024) scan_kernel()
{
    __shared__ int s[1024];
    const int b = blockIdx.x;
    const int tid = threadIdx.x;
    const int v = (tid < NCELL) ? g_cellcnt[b * NCELL + tid] : 0;
    s[tid] = v;
    __syncthreads();
    #pragma unroll
    for (int d = 1; d < 1024; d <<= 1) {
        int t = (tid >= d) ? s[tid - d] : 0;
        __syncthreads();
        s[tid] += t;
        __syncthreads();
    }
    if (tid < NCELL) {
        const int excl = s[tid] - v;
        g_cellstart[b * (NCELL + 1) + tid] = excl;
        g_cellofs[b * NCELL + tid] = excl;
    }
    if (tid == NCELL - 1)
        g_cellstart[b * (NCELL + 1) + NCELL] = s[tid];
}

__global__ void scatter_kernel(const float* __restrict__ xyz)
{
    const int b = blockIdx.y;
    const int n = blockIdx.x * 256 + threadIdx.x;
    const float x = xyz[(b * 3 + 0) * NN + n];
    const float y = xyz[(b * 3 + 1) * NN + n];
    const float z = xyz[(b * 3 + 2) * NN + n];
    const int pos = atomicAdd(&g_cellofs[b * NCELL + cell_of(x, y, z)], 1);
    g_cellpts[b * NN + pos] = make_float4(x, y, z, __int_as_float(n));
}

// ---------------------------------------------------------------------------
// Bitonic sorts (ascending) over warp registers
// ---------------------------------------------------------------------------
__device__ __forceinline__ void cmpex(int& v, int e_lane_bits, int j, int k, int lane)
{
    const int pv = __shfl_xor_sync(0xffffffffu, v, j);
    const bool up = ((e_lane_bits & k) == 0);
    const bool lo = ((lane & j) == 0);
    v = ((lo == up) ? min(v, pv) : max(v, pv));
}

__device__ __forceinline__ void bitonic64(int& v0, int& v1, int lane)
{
    #pragma unroll
    for (int k = 2; k <= 64; k <<= 1) {
        #pragma unroll
        for (int j = k >> 1; j > 0; j >>= 1) {
            if (j >= 32) {                        // k==64, j==32: up for all
                const int a = min(v0, v1), b2 = max(v0, v1);
                v0 = a; v1 = b2;
            } else {
                cmpex(v0, lane,      j, k, lane);
                cmpex(v1, 32 + lane, j, k, lane);
            }
        }
    }
}

__device__ __forceinline__ void bitonic128(int& v0, int& v1, int& v2, int& v3, int lane)
{
    #pragma unroll
    for (int k = 2; k <= 128; k <<= 1) {
        #pragma unroll
        for (int j = k >> 1; j > 0; j >>= 1) {
            if (j == 64) {                        // k==128: up everywhere
                int a, b2;
                a = min(v0, v2); b2 = max(v0, v2); v0 = a; v2 = b2;
                a = min(v1, v3); b2 = max(v1, v3); v1 = a; v3 = b2;
            } else if (j == 32) {
                // pair (v0,v1): e&k uses e=lane; pair (v2,v3): e=64+lane
                const bool upA = (((lane)      & k) == 0);
                const bool upB = (((64 + lane) & k) == 0);
                int a, b2;
                a = min(v0, v1); b2 = max(v0, v1);
                v0 = upA ? a : b2;  v1 = upA ? b2 : a;
                a = min(v2, v3); b2 = max(v2, v3);
                v2 = upB ? a : b2;  v3 = upB ? b2 : a;
            } else {
                cmpex(v0, lane,      j, k, lane);
                cmpex(v1, 32 + lane, j, k, lane);
                cmpex(v2, 64 + lane, j, k, lane);
                cmpex(v3, 96 + lane, j, k, lane);
            }
        }
    }
}

// ---------------------------------------------------------------------------
// Kernel B': cell-grid ball query. One warp per query.
// d2 is bit-exact vs reference (validated in R3): norms rn mul/add, dot =
// sequential fp32 FMA chain, d2 = (sq+sp) - 2*dot. Cells are a superset
// filter only; hits are sorted ascending to replicate top-64-smallest-index.
// ---------------------------------------------------------------------------
__global__ void __launch_bounds__(256) ballquery_cells_kernel(
    const float* __restrict__ new_xyz)
{
    __shared__ int hlist[8][HCAP];
    const int b    = blockIdx.y;
    const int warp = threadIdx.x >> 5;
    const int lane = threadIdx.x & 31;
    const int m    = blockIdx.x * 8 + warp;
    const int q    = b * MM + m;

    const float qx = new_xyz[(b * 3 + 0) * MM + m];
    const float qy = new_xyz[(b * 3 + 1) * MM + m];
    const float qz = new_xyz[(b * 3 + 2) * MM + m];
    const float sq = __fadd_rn(__fadd_rn(__fmul_rn(qx, qx), __fmul_rn(qy, qy)),
                               __fmul_rn(qz, qz));

    const int xlo = max(0, (int)floorf((qx - RREACH) * 10.0f));
    const int xhi = min(9, (int)floorf((qx + RREACH) * 10.0f));
    const int ylo = max(0, (int)floorf((qy - RREACH) * 10.0f));
    const int yhi = min(9, (int)floorf((qy + RREACH) * 10.0f));
    const int zlo = max(0, (int)floorf((qz - RREACH) * 10.0f));
    const int zhi = min(9, (int)floorf((qz + RREACH) * 10.0f));

    const unsigned lt_mask = (lane == 0) ? 0u : (0xffffffffu >> (32 - lane));
    int cnt = 0;

    for (int cx = xlo; cx <= xhi; ++cx) {
        for (int cy = ylo; cy <= yhi; ++cy) {
            const int idbase = (cx * 10 + cy) * 10;
            const int s = g_cellstart[b * (NCELL + 1) + idbase + zlo];
            const int e = g_cellstart[b * (NCELL + 1) + idbase + zhi + 1];
            for (int i = s; i < e; i += 32) {
                const int j = i + lane;
                bool in = false;
                int  pidx = 0;
                if (j < e) {
                    const float4 p = g_cellpts[b * NN + j];
                    const float sp = __fadd_rn(
                        __fadd_rn(__fmul_rn(p.x, p.x), __fmul_rn(p.y, p.y)),
                        __fmul_rn(p.z, p.z));
                    float dt = __fmul_rn(qx, p.x);
                    dt = __fmaf_rn(qy, p.y, dt);
                    dt = __fmaf_rn(qz, p.z, dt);
                    const float d2 = __fsub_rn(__fadd_rn(sq, sp),
                                               __fmul_rn(2.0f, dt));
                    in = d2 < R2;
                    pidx = __float_as_int(p.w);
                }
                const unsigned mask = __ballot_sync(0xffffffffu, in);
                if (in) {
                    const int pos = cnt + __popc(mask & lt_mask);
                    if (pos < HCAP) hlist[warp][pos] = pidx;
                }
                cnt += __popc(mask);
            }
        }
    }
    if (cnt > HCAP) cnt = HCAP;

    // sort hit indices ascending, pad with INT_MAX
    int v0 = (lane < cnt)      ? hlist[warp][lane]      : INT_MAX;
    int v1 = (32 + lane < cnt) ? hlist[warp][32 + lane] : INT_MAX;
    if (cnt <= 64) {
        bitonic64(v0, v1, lane);
    } else {
        int v2 = (64 + lane < cnt) ? hlist[warp][64 + lane] : INT_MAX;
        int v3 = (96 + lane < cnt) ? hlist[warp][96 + lane] : INT_MAX;
        bitonic128(v0, v1, v2, v3, lane);
    }

    const int f0 = __shfl_sync(0xffffffffu, v0, 0);
    const int first = (cnt == 0) ? 0 : f0;
    g_idx[q * 64 + lane]      = (lane < cnt)      ? v0 : first;
    g_idx[q * 64 + 32 + lane] = (32 + lane < cnt) ? v1 : first;
}

// ---------------------------------------------------------------------------
// Kernel A: transpose feature [B][C][N] + xyz [B][3][N] into point-major rows
// (unchanged from passing R3)
// ---------------------------------------------------------------------------
__global__ void __launch_bounds__(256) transpose_kernel(
    const float* __restrict__ xyz, const float* __restrict__ feat)
{
    __shared__ float s[64][65];
    const int b  = blockIdx.y;
    const int n0 = blockIdx.x * 64;
    const int tid = threadIdx.x;
    const int p  = tid & 63;
    const int c0 = tid >> 6;

    #pragma unroll
    for (int cc = 0; cc < 64; cc += 4) {
        const int c = cc + c0;
        s[c][p] = feat[((size_t)(b * 64 + c)) * NN + n0 + p];
    }
    __syncthreads();

    #pragma unroll
    for (int it = 0; it < 16; ++it) {
        const int o  = it * 256 + tid;
        const int pp = o >> 6;
        const int c  = o & 63;
        g_ptsT[((size_t)(b * NN + n0 + pp)) * ROWSTRIDE + 4 + c] = s[c][pp];
    }

    if (tid < 192) {
        const int c  = tid >> 6;
        const int pp = tid & 63;
        g_ptsT[((size_t)(b * NN + n0 + pp)) * ROWSTRIDE + c] =
            xyz[((size_t)(b * 3 + c)) * NN + n0 + pp];
    }
}

// ---------------------------------------------------------------------------
// Kernel C: gather + concat (unchanged from passing R3)
// ---------------------------------------------------------------------------
__global__ void __launch_bounds__(256) gather_kernel(
    const float* __restrict__ new_xyz, float* __restrict__ out)
{
    __shared__ int   sidx[64];
    __shared__ float srow[64][73];
    const int b   = blockIdx.y;
    const int m   = blockIdx.x;
    const int tid = threadIdx.x;
    const int q   = b * MM + m;

    if (tid < 64) sidx[tid] = g_idx[q * 64 + tid];
    __syncthreads();

    for (int f = tid; f < 64 * ROWSTRIDE; f += 256) {
        const int r   = f / ROWSTRIDE;
        const int col = f - r * ROWSTRIDE;
        srow[r][col] = g_ptsT[((size_t)(b * NN + sidx[r])) * ROWSTRIDE + col];
    }
    __syncthreads();

    for (int o = tid; o < 67 * 64; o += 256) {
        const int c = o >> 6;
        const int k = o & 63;
        float v;
        if (c < 3) v = srow[k][c] - new_xyz[(b * 3 + c) * MM + m];
        else       v = srow[k][c + 1];
        out[(((size_t)b * 67 + c) * MM + m) * 64 + k] = v;
    }
}

// ---------------------------------------------------------------------------
extern "C" void kernel_launch(void* const* d_in, const int* in_sizes, int n_in,
                              void* d_out, int out_size)
{
    const float* new_xyz = (const float*)d_in[0];  // (8, 3, 2048)
    const float* xyz     = (const float*)d_in[1];  // (8, 3, 8192)
    const float* feature = (const float*)d_in[2];  // (8, 64, 8192)
    float* out = (float*)d_out;                    // (8, 67, 2048, 64)

    zero_kernel<<<BB, 1024>>>();
    hist_kernel<<<dim3(NN / 256, BB), 256>>>(xyz);
    scan_kernel<<<BB, 1024>>>();
    scatter_kernel<<<dim3(NN / 256, BB), 256>>>(xyz);
    ballquery_cells_kernel<<<dim3(MM / 8, BB), 256>>>(new_xyz);
    transpose_kernel<<<dim3(NN / 64, BB), 256>>>(xyz, feature);
    gather_kernel<<<dim3(MM, BB), 256>>>(new_xyz, out);
}

// round 5
// speedup vs baseline: 1.9690x; 1.2999x over previous
#include <cuda_runtime.h>
#include <limits.h>

#define BB 8
#define NN 8192
#define MM 2048
#define CC 64
#define KK 64
#define R2 0.01f
#define ROWF 68            // floats per point row: [x,y,z, f0..f63, pad] (272B)
#define NCELL 1000         // 10x10x10 grid, cell size 0.1
#define RREACH 0.1002f     // conservative cell reach (covers d2 rounding slack)
#define HCAP 128           // per-query candidate-hit cap (max expected ~75)

// Scratch (no cudaMalloc allowed)
__device__ float  g_ptsT[BB * NN * ROWF];        // transposed point rows
__device__ int    g_idx[BB * MM * KK];           // neighbor indices
__device__ int    g_cellstart[BB * (NCELL + 1)];
__device__ float4 g_cellpts[BB * NN];            // (x,y,z, idx-bits) cell-sorted

__device__ __forceinline__ int cell_of(float x, float y, float z)
{
    int cx = (int)(x * 10.0f); cx = min(max(cx, 0), 9);
    int cy = (int)(y * 10.0f); cy = min(max(cy, 0), 9);
    int cz = (int)(z * 10.0f); cz = min(max(cz, 0), 9);
    return (cx * 10 + cy) * 10 + cz;
}

// ---------------------------------------------------------------------------
// Fused grid build: one block per batch. smem hist -> scan -> smem scatter.
// ---------------------------------------------------------------------------
__global__ void __launch_bounds__(1024) build_grid_kernel(const float* __restrict__ xyz)
{
    __shared__ int scnt[1024];
    __shared__ int sofs[NCELL];
    const int b   = blockIdx.x;
    const int tid = threadIdx.x;

    scnt[tid] = 0;
    __syncthreads();

    float px[8], py[8], pz[8];
    int   pc[8];
    #pragma unroll
    for (int i = 0; i < 8; ++i) {
        const int n = i * 1024 + tid;
        px[i] = xyz[(b * 3 + 0) * NN + n];
        py[i] = xyz[(b * 3 + 1) * NN + n];
        pz[i] = xyz[(b * 3 + 2) * NN + n];
        pc[i] = cell_of(px[i], py[i], pz[i]);
        atomicAdd(&scnt[pc[i]], 1);
    }
    __syncthreads();

    // Hillis-Steele inclusive scan over 1024 (cells 1000..1023 are zero)
    const int v = scnt[tid];
    #pragma unroll
    for (int d = 1; d < 1024; d <<= 1) {
        const int t = (tid >= d) ? scnt[tid - d] : 0;
        __syncthreads();
        scnt[tid] += t;
        __syncthreads();
    }
    if (tid < NCELL) {
        const int excl = scnt[tid] - v;
        g_cellstart[b * (NCELL + 1) + tid] = excl;
        sofs[tid] = excl;
    }
    if (tid == NCELL - 1)
        g_cellstart[b * (NCELL + 1) + NCELL] = scnt[tid];
    __syncthreads();

    #pragma unroll
    for (int i = 0; i < 8; ++i) {
        const int n   = i * 1024 + tid;
        const int pos = atomicAdd(&sofs[pc[i]], 1);
        g_cellpts[b * NN + pos] = make_float4(px[i], py[i], pz[i], __int_as_float(n));
    }
}

// ---------------------------------------------------------------------------
// Bitonic sorts (ascending) over warp registers (unchanged from R4)
// ---------------------------------------------------------------------------
__device__ __forceinline__ void cmpex(int& v, int e_lane_bits, int j, int k, int lane)
{
    const int pv = __shfl_xor_sync(0xffffffffu, v, j);
    const bool up = ((e_lane_bits & k) == 0);
    const bool lo = ((lane & j) == 0);
    v = ((lo == up) ? min(v, pv) : max(v, pv));
}

__device__ __forceinline__ void bitonic64(int& v0, int& v1, int lane)
{
    #pragma unroll
    for (int k = 2; k <= 64; k <<= 1) {
        #pragma unroll
        for (int j = k >> 1; j > 0; j >>= 1) {
            if (j >= 32) {
                const int a = min(v0, v1), b2 = max(v0, v1);
                v0 = a; v1 = b2;
            } else {
                cmpex(v0, lane,      j, k, lane);
                cmpex(v1, 32 + lane, j, k, lane);
            }
        }
    }
}

__device__ __forceinline__ void bitonic128(int& v0, int& v1, int& v2, int& v3, int lane)
{
    #pragma unroll
    for (int k = 2; k <= 128; k <<= 1) {
        #pragma unroll
        for (int j = k >> 1; j > 0; j >>= 1) {
            if (j == 64) {
                int a, b2;
                a = min(v0, v2); b2 = max(v0, v2); v0 = a; v2 = b2;
                a = min(v1, v3); b2 = max(v1, v3); v1 = a; v3 = b2;
            } else if (j == 32) {
                const bool upA = (((lane)      & k) == 0);
                const bool upB = (((64 + lane) & k) == 0);
                int a, b2;
                a = min(v0, v1); b2 = max(v0, v1);
                v0 = upA ? a : b2;  v1 = upA ? b2 : a;
                a = min(v2, v3); b2 = max(v2, v3);
                v2 = upB ? a : b2;  v3 = upB ? b2 : a;
            } else {
                cmpex(v0, lane,      j, k, lane);
                cmpex(v1, 32 + lane, j, k, lane);
                cmpex(v2, 64 + lane, j, k, lane);
                cmpex(v3, 96 + lane, j, k, lane);
            }
        }
    }
}

// ---------------------------------------------------------------------------
// Ball query (unchanged logic from passing R4). d2 is bit-exact vs reference:
// norms rn mul/add, dot = sequential fp32 FMA chain, d2 = (sq+sp) - 2*dot.
// ---------------------------------------------------------------------------
__global__ void __launch_bounds__(256) ballquery_cells_kernel(
    const float* __restrict__ new_xyz)
{
    __shared__ int hlist[8][HCAP];
    const int b    = blockIdx.y;
    const int warp = threadIdx.x >> 5;
    const int lane = threadIdx.x & 31;
    const int m    = blockIdx.x * 8 + warp;
    const int q    = b * MM + m;

    const float qx = new_xyz[(b * 3 + 0) * MM + m];
    const float qy = new_xyz[(b * 3 + 1) * MM + m];
    const float qz = new_xyz[(b * 3 + 2) * MM + m];
    const float sq = __fadd_rn(__fadd_rn(__fmul_rn(qx, qx), __fmul_rn(qy, qy)),
                               __fmul_rn(qz, qz));

    const int xlo = max(0, (int)floorf((qx - RREACH) * 10.0f));
    const int xhi = min(9, (int)floorf((qx + RREACH) * 10.0f));
    const int ylo = max(0, (int)floorf((qy - RREACH) * 10.0f));
    const int yhi = min(9, (int)floorf((qy + RREACH) * 10.0f));
    const int zlo = max(0, (int)floorf((qz - RREACH) * 10.0f));
    const int zhi = min(9, (int)floorf((qz + RREACH) * 10.0f));

    const unsigned lt_mask = (lane == 0) ? 0u : (0xffffffffu >> (32 - lane));
    int cnt = 0;

    for (int cx = xlo; cx <= xhi; ++cx) {
        for (int cy = ylo; cy <= yhi; ++cy) {
            const int idbase = (cx * 10 + cy) * 10;
            const int s = g_cellstart[b * (NCELL + 1) + idbase + zlo];
            const int e = g_cellstart[b * (NCELL + 1) + idbase + zhi + 1];
            for (int i = s; i < e; i += 32) {
                const int j = i + lane;
                bool in = false;
                int  pidx = 0;
                if (j < e) {
                    const float4 p = g_cellpts[b * NN + j];
                    const float sp = __fadd_rn(
                        __fadd_rn(__fmul_rn(p.x, p.x), __fmul_rn(p.y, p.y)),
                        __fmul_rn(p.z, p.z));
                    float dt = __fmul_rn(qx, p.x);
                    dt = __fmaf_rn(qy, p.y, dt);
                    dt = __fmaf_rn(qz, p.z, dt);
                    const float d2 = __fsub_rn(__fadd_rn(sq, sp),
                                               __fmul_rn(2.0f, dt));
                    in = d2 < R2;
                    pidx = __float_as_int(p.w);
                }
                const unsigned mask = __ballot_sync(0xffffffffu, in);
                if (in) {
                    const int pos = cnt + __popc(mask & lt_mask);
                    if (pos < HCAP) hlist[warp][pos] = pidx;
                }
                cnt += __popc(mask);
            }
        }
    }
    if (cnt > HCAP) cnt = HCAP;

    int v0 = (lane < cnt)      ? hlist[warp][lane]      : INT_MAX;
    int v1 = (32 + lane < cnt) ? hlist[warp][32 + lane] : INT_MAX;
    if (cnt <= 64) {
        bitonic64(v0, v1, lane);
    } else {
        int v2 = (64 + lane < cnt) ? hlist[warp][64 + lane] : INT_MAX;
        int v3 = (96 + lane < cnt) ? hlist[warp][96 + lane] : INT_MAX;
        bitonic128(v0, v1, v2, v3, lane);
    }

    const int f0 = __shfl_sync(0xffffffffu, v0, 0);
    const int first = (cnt == 0) ? 0 : f0;
    g_idx[q * 64 + lane]      = (lane < cnt)      ? v0 : first;
    g_idx[q * 64 + 32 + lane] = (32 + lane < cnt) ? v1 : first;
}

// ---------------------------------------------------------------------------
// Transpose: build point-major rows [x,y,z,f0..f63,pad] with STG.128.
// ---------------------------------------------------------------------------
__global__ void __launch_bounds__(256) transpose_kernel(
    const float* __restrict__ xyz, const float* __restrict__ feat)
{
    __shared__ float s[64][65];      // features, padded
    __shared__ float sxyz[3][64];
    const int b   = blockIdx.y;
    const int n0  = blockIdx.x * 64;
    const int tid = threadIdx.x;
    const int p   = tid & 63;
    const int c0  = tid >> 6;

    #pragma unroll
    for (int cc = 0; cc < 64; cc += 4) {
        const int c = cc + c0;
        s[c][p] = feat[((size_t)(b * 64 + c)) * NN + n0 + p];
    }
    if (tid < 192) {
        const int c  = tid >> 6;
        const int pp = tid & 63;
        sxyz[c][pp] = xyz[((size_t)(b * 3 + c)) * NN + n0 + pp];
    }
    __syncthreads();

    // 64 rows x 17 float4 writes
    for (int f = tid; f < 64 * 17; f += 256) {
        const int pp = f / 17;
        const int j  = f - pp * 17;
        float4 v;
        if (j == 0) {
            v.x = sxyz[0][pp]; v.y = sxyz[1][pp]; v.z = sxyz[2][pp]; v.w = s[0][pp];
        } else if (j == 16) {
            v.x = s[61][pp]; v.y = s[62][pp]; v.z = s[63][pp]; v.w = 0.0f;
        } else {
            const int c = 4 * j - 3;
            v.x = s[c][pp]; v.y = s[c + 1][pp]; v.z = s[c + 2][pp]; v.w = s[c + 3][pp];
        }
        ((float4*)(g_ptsT + ((size_t)(b * NN + n0 + pp)) * ROWF))[j] = v;
    }
}

// ---------------------------------------------------------------------------
// Gather + concat: vectorized. LDG.128 staging, STG.128 output over k.
// smem row stride 69 (odd): conflict-light column reads.
// ---------------------------------------------------------------------------
__global__ void __launch_bounds__(256) gather_kernel(
    const float* __restrict__ new_xyz, float* __restrict__ out)
{
    __shared__ int   sidx[64];
    __shared__ float srow[64][69];
    const int b   = blockIdx.y;
    const int m   = blockIdx.x;
    const int tid = threadIdx.x;
    const int q   = b * MM + m;

    if (tid < 64) sidx[tid] = g_idx[q * 64 + tid];
    __syncthreads();

    // stage: 64 rows x 17 float4 (272B contiguous per row, L2-resident)
    for (int f = tid; f < 64 * 17; f += 256) {
        const int r = f / 17;
        const int j = f - r * 17;
        const float4 v = ((const float4*)(g_ptsT +
                          (size_t)(b * NN + sidx[r]) * ROWF))[j];
        srow[r][4 * j + 0] = v.x;
        srow[r][4 * j + 1] = v.y;
        srow[r][4 * j + 2] = v.z;
        srow[r][4 * j + 3] = v.w;
    }
    __syncthreads();

    // output: 67 c x 16 k4 float4, fully coalesced STG.128
    for (int o = tid; o < 67 * 16; o += 256) {
        const int c  = o >> 4;
        const int k4 = o & 15;
        const int k  = k4 * 4;
        float4 v;
        v.x = srow[k + 0][c];
        v.y = srow[k + 1][c];
        v.z = srow[k + 2][c];
        v.w = srow[k + 3][c];
        if (c < 3) {
            const float sub = new_xyz[(b * 3 + c) * MM + m];
            v.x -= sub; v.y -= sub; v.z -= sub; v.w -= sub;
        }
        ((float4*)(out + (((size_t)b * 67 + c) * MM + m) * 64))[k4] = v;
    }
}

// ---------------------------------------------------------------------------
extern "C" void kernel_launch(void* const* d_in, const int* in_sizes, int n_in,
                              void* d_out, int out_size)
{
    const float* new_xyz = (const float*)d_in[0];  // (8, 3, 2048)
    const float* xyz     = (const float*)d_in[1];  // (8, 3, 8192)
    const float* feature = (const float*)d_in[2];  // (8, 64, 8192)
    float* out = (float*)d_out;                    // (8, 67, 2048, 64)

    build_grid_kernel<<<BB, 1024>>>(xyz);
    ballquery_cells_kernel<<<dim3(MM / 8, BB), 256>>>(new_xyz);
    transpose_kernel<<<dim3(NN / 64, BB), 256>>>(xyz, feature);
    gather_kernel<<<dim3(MM, BB), 256>>>(new_xyz, out);
}

// round 6
// speedup vs baseline: 2.0606x; 1.0465x over previous
#include <cuda_runtime.h>
#include <limits.h>

#define BB 8
#define NN 8192
#define MM 2048
#define CC 64
#define KK 64
#define R2 0.01f
#define ROWF 68            // floats per row: [f0..f63, x, y, z, pad] (272B)
#define NCELL 1000         // 10x10x10 grid, cell size 0.1
#define RREACH 0.1002f     // conservative cell reach (covers d2 rounding slack)
#define HCAP 128           // per-query candidate-hit cap (max expected ~75)

// Scratch (no cudaMalloc allowed)
__device__ float  g_ptsT[BB * NN * ROWF];        // transposed point rows
__device__ int    g_idx[BB * MM * KK];           // neighbor indices
__device__ int    g_cellstart[BB * (NCELL + 1)];
__device__ float4 g_cellpts[BB * NN];            // (x,y,z, idx-bits) cell-sorted

__device__ __forceinline__ int cell_of(float x, float y, float z)
{
    int cx = (int)(x * 10.0f); cx = min(max(cx, 0), 9);
    int cy = (int)(y * 10.0f); cy = min(max(cy, 0), 9);
    int cz = (int)(z * 10.0f); cz = min(max(cz, 0), 9);
    return (cx * 10 + cy) * 10 + cz;
}

// ---------------------------------------------------------------------------
// Fused grid build (unchanged from passing R5)
// ---------------------------------------------------------------------------
__global__ void __launch_bounds__(1024) build_grid_kernel(const float* __restrict__ xyz)
{
    __shared__ int scnt[1024];
    __shared__ int sofs[NCELL];
    const int b   = blockIdx.x;
    const int tid = threadIdx.x;

    scnt[tid] = 0;
    __syncthreads();

    float px[8], py[8], pz[8];
    int   pc[8];
    #pragma unroll
    for (int i = 0; i < 8; ++i) {
        const int n = i * 1024 + tid;
        px[i] = xyz[(b * 3 + 0) * NN + n];
        py[i] = xyz[(b * 3 + 1) * NN + n];
        pz[i] = xyz[(b * 3 + 2) * NN + n];
        pc[i] = cell_of(px[i], py[i], pz[i]);
        atomicAdd(&scnt[pc[i]], 1);
    }
    __syncthreads();

    const int v = scnt[tid];
    #pragma unroll
    for (int d = 1; d < 1024; d <<= 1) {
        const int t = (tid >= d) ? scnt[tid - d] : 0;
        __syncthreads();
        scnt[tid] += t;
        __syncthreads();
    }
    if (tid < NCELL) {
        const int excl = scnt[tid] - v;
        g_cellstart[b * (NCELL + 1) + tid] = excl;
        sofs[tid] = excl;
    }
    if (tid == NCELL - 1)
        g_cellstart[b * (NCELL + 1) + NCELL] = scnt[tid];
    __syncthreads();

    #pragma unroll
    for (int i = 0; i < 8; ++i) {
        const int n   = i * 1024 + tid;
        const int pos = atomicAdd(&sofs[pc[i]], 1);
        g_cellpts[b * NN + pos] = make_float4(px[i], py[i], pz[i], __int_as_float(n));
    }
}

// ---------------------------------------------------------------------------
// Bitonic sorts (unchanged)
// ---------------------------------------------------------------------------
__device__ __forceinline__ void cmpex(int& v, int e_lane_bits, int j, int k, int lane)
{
    const int pv = __shfl_xor_sync(0xffffffffu, v, j);
    const bool up = ((e_lane_bits & k) == 0);
    const bool lo = ((lane & j) == 0);
    v = ((lo == up) ? min(v, pv) : max(v, pv));
}

__device__ __forceinline__ void bitonic64(int& v0, int& v1, int lane)
{
    #pragma unroll
    for (int k = 2; k <= 64; k <<= 1) {
        #pragma unroll
        for (int j = k >> 1; j > 0; j >>= 1) {
            if (j >= 32) {
                const int a = min(v0, v1), b2 = max(v0, v1);
                v0 = a; v1 = b2;
            } else {
                cmpex(v0, lane,      j, k, lane);
                cmpex(v1, 32 + lane, j, k, lane);
            }
        }
    }
}

__device__ __forceinline__ void bitonic128(int& v0, int& v1, int& v2, int& v3, int lane)
{
    #pragma unroll
    for (int k = 2; k <= 128; k <<= 1) {
        #pragma unroll
        for (int j = k >> 1; j > 0; j >>= 1) {
            if (j == 64) {
                int a, b2;
                a = min(v0, v2); b2 = max(v0, v2); v0 = a; v2 = b2;
                a = min(v1, v3); b2 = max(v1, v3); v1 = a; v3 = b2;
            } else if (j == 32) {
                const bool upA = (((lane)      & k) == 0);
                const bool upB = (((64 + lane) & k) == 0);
                int a, b2;
                a = min(v0, v1); b2 = max(v0, v1);
                v0 = upA ? a : b2;  v1 = upA ? b2 : a;
                a = min(v2, v3); b2 = max(v2, v3);
                v2 = upB ? a : b2;  v3 = upB ? b2 : a;
            } else {
                cmpex(v0, lane,      j, k, lane);
                cmpex(v1, 32 + lane, j, k, lane);
                cmpex(v2, 64 + lane, j, k, lane);
                cmpex(v3, 96 + lane, j, k, lane);
            }
        }
    }
}

// ---------------------------------------------------------------------------
// Ball query (unchanged from passing R5). d2 bit-exact vs reference.
// ---------------------------------------------------------------------------
__global__ void __launch_bounds__(256) ballquery_cells_kernel(
    const float* __restrict__ new_xyz)
{
    __shared__ int hlist[8][HCAP];
    const int b    = blockIdx.y;
    const int warp = threadIdx.x >> 5;
    const int lane = threadIdx.x & 31;
    const int m    = blockIdx.x * 8 + warp;
    const int q    = b * MM + m;

    const float qx = new_xyz[(b * 3 + 0) * MM + m];
    const float qy = new_xyz[(b * 3 + 1) * MM + m];
    const float qz = new_xyz[(b * 3 + 2) * MM + m];
    const float sq = __fadd_rn(__fadd_rn(__fmul_rn(qx, qx), __fmul_rn(qy, qy)),
                               __fmul_rn(qz, qz));

    const int xlo = max(0, (int)floorf((qx - RREACH) * 10.0f));
    const int xhi = min(9, (int)floorf((qx + RREACH) * 10.0f));
    const int ylo = max(0, (int)floorf((qy - RREACH) * 10.0f));
    const int yhi = min(9, (int)floorf((qy + RREACH) * 10.0f));
    const int zlo = max(0, (int)floorf((qz - RREACH) * 10.0f));
    const int zhi = min(9, (int)floorf((qz + RREACH) * 10.0f));

    const unsigned lt_mask = (lane == 0) ? 0u : (0xffffffffu >> (32 - lane));
    int cnt = 0;

    for (int cx = xlo; cx <= xhi; ++cx) {
        for (int cy = ylo; cy <= yhi; ++cy) {
            const int idbase = (cx * 10 + cy) * 10;
            const int s = g_cellstart[b * (NCELL + 1) + idbase + zlo];
            const int e = g_cellstart[b * (NCELL + 1) + idbase + zhi + 1];
            for (int i = s; i < e; i += 32) {
                const int j = i + lane;
                bool in = false;
                int  pidx = 0;
                if (j < e) {
                    const float4 p = g_cellpts[b * NN + j];
                    const float sp = __fadd_rn(
                        __fadd_rn(__fmul_rn(p.x, p.x), __fmul_rn(p.y, p.y)),
                        __fmul_rn(p.z, p.z));
                    float dt = __fmul_rn(qx, p.x);
                    dt = __fmaf_rn(qy, p.y, dt);
                    dt = __fmaf_rn(qz, p.z, dt);
                    const float d2 = __fsub_rn(__fadd_rn(sq, sp),
                                               __fmul_rn(2.0f, dt));
                    in = d2 < R2;
                    pidx = __float_as_int(p.w);
                }
                const unsigned mask = __ballot_sync(0xffffffffu, in);
                if (in) {
                    const int pos = cnt + __popc(mask & lt_mask);
                    if (pos < HCAP) hlist[warp][pos] = pidx;
                }
                cnt += __popc(mask);
            }
        }
    }
    if (cnt > HCAP) cnt = HCAP;

    int v0 = (lane < cnt)      ? hlist[warp][lane]      : INT_MAX;
    int v1 = (32 + lane < cnt) ? hlist[warp][32 + lane] : INT_MAX;
    if (cnt <= 64) {
        bitonic64(v0, v1, lane);
    } else {
        int v2 = (64 + lane < cnt) ? hlist[warp][64 + lane] : INT_MAX;
        int v3 = (96 + lane < cnt) ? hlist[warp][96 + lane] : INT_MAX;
        bitonic128(v0, v1, v2, v3, lane);
    }

    const int f0 = __shfl_sync(0xffffffffu, v0, 0);
    const int first = (cnt == 0) ? 0 : f0;
    g_idx[q * 64 + lane]      = (lane < cnt)      ? v0 : first;
    g_idx[q * 64 + 32 + lane] = (32 + lane < cnt) ? v1 : first;
}

// ---------------------------------------------------------------------------
// Transpose: build rows [f0..f63, x, y, z, pad] with STG.128.
// ---------------------------------------------------------------------------
__global__ void __launch_bounds__(256) transpose_kernel(
    const float* __restrict__ xyz, const float* __restrict__ feat)
{
    __shared__ float s[64][65];      // features, padded
    __shared__ float sxyz[3][64];
    const int b   = blockIdx.y;
    const int n0  = blockIdx.x * 64;
    const int tid = threadIdx.x;
    const int p   = tid & 63;
    const int c0  = tid >> 6;

    #pragma unroll
    for (int cc = 0; cc < 64; cc += 4) {
        const int c = cc + c0;
        s[c][p] = feat[((size_t)(b * 64 + c)) * NN + n0 + p];
    }
    if (tid < 192) {
        const int c  = tid >> 6;
        const int pp = tid & 63;
        sxyz[c][pp] = xyz[((size_t)(b * 3 + c)) * NN + n0 + pp];
    }
    __syncthreads();

    // 64 rows x 17 float4 writes: quads 0..15 = features, quad 16 = xyz
    for (int f = tid; f < 64 * 17; f += 256) {
        const int pp = f / 17;
        const int j  = f - pp * 17;
        float4 v;
        if (j < 16) {
            const int c = 4 * j;
            v.x = s[c][pp]; v.y = s[c + 1][pp]; v.z = s[c + 2][pp]; v.w = s[c + 3][pp];
        } else {
            v.x = sxyz[0][pp]; v.y = sxyz[1][pp]; v.z = sxyz[2][pp]; v.w = 0.0f;
        }
        ((float4*)(g_ptsT + ((size_t)(b * NN + n0 + pp)) * ROWF))[j] = v;
    }
}

// ---------------------------------------------------------------------------
// Gather + concat: conflict-free swizzled smem transpose.
// Feature float (k, c) stored at srow[k][c ^ (k&31)]; staged via STS.128
// (quad j -> j ^ ((k>>2)&7), components XOR-permuted by k&3).
// Output warps cover 4 c x 8 k4 -> column LDS reads hit 32 distinct banks.
// ---------------------------------------------------------------------------
__global__ void __launch_bounds__(256) gather_kernel(
    const float* __restrict__ new_xyz, float* __restrict__ out)
{
    __shared__ int   sidx[64];
    __shared__ float srow[64][ROWF];
    const int b   = blockIdx.y;
    const int m   = blockIdx.x;
    const int tid = threadIdx.x;
    const int q   = b * MM + m;

    if (tid < 64) sidx[tid] = g_idx[q * 64 + tid];
    __syncthreads();

    // stage: 64 rows x 17 quads. LDG.128 -> swizzled STS.128 / xyz scalars.
    for (int f = tid; f < 64 * 17; f += 256) {
        const int r = f / 17;
        const int j = f - r * 17;
        float4 v = ((const float4*)(g_ptsT +
                    (size_t)(b * NN + sidx[r]) * ROWF))[j];
        if (j < 16) {
            // component XOR-permute by r&3: w[t] = v[t ^ (r&3)]
            if (r & 1) { float t = v.x; v.x = v.y; v.y = t;
                         t = v.z; v.z = v.w; v.w = t; }
            if (r & 2) { float t = v.x; v.x = v.z; v.z = t;
                         t = v.y; v.y = v.w; v.w = t; }
            const int jq = j ^ ((r >> 2) & 7);
            *((float4*)&srow[r][4 * jq]) = v;
        } else {
            srow[r][64] = v.x;   // x
            srow[r][65] = v.y;   // y
            srow[r][66] = v.z;   // z
        }
    }
    __syncthreads();

    // output: tasks (c, k4h 0..7); each writes k4 = k4h and k4h+8.
    // Warp spans 4 c x 8 k4h -> conflict-free column LDS.
    for (int t = tid; t < 67 * 8; t += 256) {
        const int c   = t >> 3;
        const int k4h = t & 7;
        float sub = 0.0f;
        if (c < 3) sub = new_xyz[(b * 3 + c) * MM + m];
        #pragma unroll
        for (int h = 0; h < 2; ++h) {
            const int k4 = k4h + 8 * h;
            const int k  = 4 * k4;
            float4 v;
            if (c < 3) {
                v.x = srow[k + 0][64 + c] - sub;
                v.y = srow[k + 1][64 + c] - sub;
                v.z = srow[k + 2][64 + c] - sub;
                v.w = srow[k + 3][64 + c] - sub;
            } else {
                const int cf = c - 3;
                v.x = srow[k + 0][cf ^ ((k + 0) & 31)];
                v.y = srow[k + 1][cf ^ ((k + 1) & 31)];
                v.z = srow[k + 2][cf ^ ((k + 2) & 31)];
                v.w = srow[k + 3][cf ^ ((k + 3) & 31)];
            }
            ((float4*)(out + (((size_t)b * 67 + c) * MM + m) * 64))[k4] = v;
        }
    }
}

// ---------------------------------------------------------------------------
extern "C" void kernel_launch(void* const* d_in, const int* in_sizes, int n_in,
                              void* d_out, int out_size)
{
    const float* new_xyz = (const float*)d_in[0];  // (8, 3, 2048)
    const float* xyz     = (const float*)d_in[1];  // (8, 3, 8192)
    const float* feature = (const float*)d_in[2];  // (8, 64, 8192)
    float* out = (float*)d_out;                    // (8, 67, 2048, 64)

    build_grid_kernel<<<BB, 1024>>>(xyz);
    ballquery_cells_kernel<<<dim3(MM / 8, BB), 256>>>(new_xyz);
    transpose_kernel<<<dim3(NN / 64, BB), 256>>>(xyz, feature);
    gather_kernel<<<dim3(MM, BB), 256>>>(new_xyz, out);
}

// round 7
// speedup vs baseline: 2.1964x; 1.0659x over previous
#include <cuda_runtime.h>
#include <limits.h>

#define BB 8
#define NN 8192
#define MM 2048
#define CC 64
#define KK 64
#define R2 0.01f
#define ROWF 68            // floats per row: [f0..f63, x, y, z, pad] (272B)
#define NCELL 1000         // 10x10x10 grid, cell size 0.1
#define RREACH 0.1002f     // conservative cell reach (covers d2 rounding slack)
#define HCAP 128           // per-query candidate-hit cap (max expected ~75)
#define TPTS 128           // transpose points per block

// Scratch (no cudaMalloc allowed)
__device__ float  g_ptsT[BB * NN * ROWF];        // transposed point rows
__device__ int    g_idx[BB * MM * KK];           // neighbor indices
__device__ int    g_cellstart[BB * (NCELL + 1)];
__device__ float4 g_cellpts[BB * NN];            // (x,y,z, idx-bits) cell-sorted

__device__ __forceinline__ int cell_of(float x, float y, float z)
{
    int cx = (int)(x * 10.0f); cx = min(max(cx, 0), 9);
    int cy = (int)(y * 10.0f); cy = min(max(cy, 0), 9);
    int cz = (int)(z * 10.0f); cz = min(max(cz, 0), 9);
    return (cx * 10 + cy) * 10 + cz;
}

// ---------------------------------------------------------------------------
// K1: fused grid-build (blocks 0..7) + transpose (blocks 8..519).
// Both 1024 threads; independent work overlapped in one launch.
// ---------------------------------------------------------------------------
union SmemK1 {
    struct { int scnt[1024]; int sofs[NCELL]; } g;
    struct { float s[64][TPTS + 1]; float sxyz[3][TPTS]; } t;
};

__global__ void __launch_bounds__(1024) build_and_transpose_kernel(
    const float* __restrict__ xyz, const float* __restrict__ feat)
{
    __shared__ SmemK1 sm;
    const int tid = threadIdx.x;

    if (blockIdx.x < 8) {
        // ---- grid build (identical logic to passing R6) ----
        const int b = blockIdx.x;
        sm.g.scnt[tid] = 0;
        __syncthreads();

        float px[8], py[8], pz[8];
        int   pc[8];
        #pragma unroll
        for (int i = 0; i < 8; ++i) {
            const int n = i * 1024 + tid;
            px[i] = xyz[(b * 3 + 0) * NN + n];
            py[i] = xyz[(b * 3 + 1) * NN + n];
            pz[i] = xyz[(b * 3 + 2) * NN + n];
            pc[i] = cell_of(px[i], py[i], pz[i]);
            atomicAdd(&sm.g.scnt[pc[i]], 1);
        }
        __syncthreads();

        const int v = sm.g.scnt[tid];
        #pragma unroll
        for (int d = 1; d < 1024; d <<= 1) {
            const int t = (tid >= d) ? sm.g.scnt[tid - d] : 0;
            __syncthreads();
            sm.g.scnt[tid] += t;
            __syncthreads();
        }
        if (tid < NCELL) {
            const int excl = sm.g.scnt[tid] - v;
            g_cellstart[b * (NCELL + 1) + tid] = excl;
            sm.g.sofs[tid] = excl;
        }
        if (tid == NCELL - 1)
            g_cellstart[b * (NCELL + 1) + NCELL] = sm.g.scnt[tid];
        __syncthreads();

        #pragma unroll
        for (int i = 0; i < 8; ++i) {
            const int n   = i * 1024 + tid;
            const int pos = atomicAdd(&sm.g.sofs[pc[i]], 1);
            g_cellpts[b * NN + pos] =
                make_float4(px[i], py[i], pz[i], __int_as_float(n));
        }
    } else {
        // ---- transpose: rows [f0..f63, x, y, z, pad], 128 points/block ----
        const int idx = blockIdx.x - 8;          // 0..511
        const int b   = idx >> 6;
        const int n0  = (idx & 63) * TPTS;

        for (int i = tid; i < 64 * TPTS; i += 1024) {
            const int c = i >> 7;                // TPTS = 128
            const int p = i & (TPTS - 1);
            sm.t.s[c][p] = feat[((size_t)(b * 64 + c)) * NN + n0 + p];
        }
        if (tid < 3 * TPTS) {
            const int c = tid >> 7;
            const int p = tid & (TPTS - 1);
            sm.t.sxyz[c][p] = xyz[((size_t)(b * 3 + c)) * NN + n0 + p];
        }
        __syncthreads();

        for (int f = tid; f < TPTS * 17; f += 1024) {
            const int pp = f / 17;
            const int j  = f - pp * 17;
            float4 v;
            if (j < 16) {
                const int c = 4 * j;
                v.x = sm.t.s[c][pp];     v.y = sm.t.s[c + 1][pp];
                v.z = sm.t.s[c + 2][pp]; v.w = sm.t.s[c + 3][pp];
            } else {
                v.x = sm.t.sxyz[0][pp]; v.y = sm.t.sxyz[1][pp];
                v.z = sm.t.sxyz[2][pp]; v.w = 0.0f;
            }
            ((float4*)(g_ptsT + ((size_t)(b * NN + n0 + pp)) * ROWF))[j] = v;
        }
    }
}

// ---------------------------------------------------------------------------
// Bitonic sorts (unchanged)
// ---------------------------------------------------------------------------
__device__ __forceinline__ void cmpex(int& v, int e_lane_bits, int j, int k, int lane)
{
    const int pv = __shfl_xor_sync(0xffffffffu, v, j);
    const bool up = ((e_lane_bits & k) == 0);
    const bool lo = ((lane & j) == 0);
    v = ((lo == up) ? min(v, pv) : max(v, pv));
}

__device__ __forceinline__ void bitonic64(int& v0, int& v1, int lane)
{
    #pragma unroll
    for (int k = 2; k <= 64; k <<= 1) {
        #pragma unroll
        for (int j = k >> 1; j > 0; j >>= 1) {
            if (j >= 32) {
                const int a = min(v0, v1), b2 = max(v0, v1);
                v0 = a; v1 = b2;
            } else {
                cmpex(v0, lane,      j, k, lane);
                cmpex(v1, 32 + lane, j, k, lane);
            }
        }
    }
}

__device__ __forceinline__ void bitonic128(int& v0, int& v1, int& v2, int& v3, int lane)
{
    #pragma unroll
    for (int k = 2; k <= 128; k <<= 1) {
        #pragma unroll
        for (int j = k >> 1; j > 0; j >>= 1) {
            if (j == 64) {
                int a, b2;
                a = min(v0, v2); b2 = max(v0, v2); v0 = a; v2 = b2;
                a = min(v1, v3); b2 = max(v1, v3); v1 = a; v3 = b2;
            } else if (j == 32) {
                const bool upA = (((lane)      & k) == 0);
                const bool upB = (((64 + lane) & k) == 0);
                int a, b2;
                a = min(v0, v1); b2 = max(v0, v1);
                v0 = upA ? a : b2;  v1 = upA ? b2 : a;
                a = min(v2, v3); b2 = max(v2, v3);
                v2 = upB ? a : b2;  v3 = upB ? b2 : a;
            } else {
                cmpex(v0, lane,      j, k, lane);
                cmpex(v1, 32 + lane, j, k, lane);
                cmpex(v2, 64 + lane, j, k, lane);
                cmpex(v3, 96 + lane, j, k, lane);
            }
        }
    }
}

// ---------------------------------------------------------------------------
// Ball query (unchanged from passing R6). d2 bit-exact vs reference.
// ---------------------------------------------------------------------------
__global__ void __launch_bounds__(256) ballquery_cells_kernel(
    const float* __restrict__ new_xyz)
{
    __shared__ int hlist[8][HCAP];
    const int b    = blockIdx.y;
    const int warp = threadIdx.x >> 5;
    const int lane = threadIdx.x & 31;
    const int m    = blockIdx.x * 8 + warp;
    const int q    = b * MM + m;

    const float qx = new_xyz[(b * 3 + 0) * MM + m];
    const float qy = new_xyz[(b * 3 + 1) * MM + m];
    const float qz = new_xyz[(b * 3 + 2) * MM + m];
    const float sq = __fadd_rn(__fadd_rn(__fmul_rn(qx, qx), __fmul_rn(qy, qy)),
                               __fmul_rn(qz, qz));

    const int xlo = max(0, (int)floorf((qx - RREACH) * 10.0f));
    const int xhi = min(9, (int)floorf((qx + RREACH) * 10.0f));
    const int ylo = max(0, (int)floorf((qy - RREACH) * 10.0f));
    const int yhi = min(9, (int)floorf((qy + RREACH) * 10.0f));
    const int zlo = max(0, (int)floorf((qz - RREACH) * 10.0f));
    const int zhi = min(9, (int)floorf((qz + RREACH) * 10.0f));

    const unsigned lt_mask = (lane == 0) ? 0u : (0xffffffffu >> (32 - lane));
    int cnt = 0;

    for (int cx = xlo; cx <= xhi; ++cx) {
        for (int cy = ylo; cy <= yhi; ++cy) {
            const int idbase = (cx * 10 + cy) * 10;
            const int s = g_cellstart[b * (NCELL + 1) + idbase + zlo];
            const int e = g_cellstart[b * (NCELL + 1) + idbase + zhi + 1];
            for (int i = s; i < e; i += 32) {
                const int j = i + lane;
                bool in = false;
                int  pidx = 0;
                if (j < e) {
                    const float4 p = g_cellpts[b * NN + j];
                    const float sp = __fadd_rn(
                        __fadd_rn(__fmul_rn(p.x, p.x), __fmul_rn(p.y, p.y)),
                        __fmul_rn(p.z, p.z));
                    float dt = __fmul_rn(qx, p.x);
                    dt = __fmaf_rn(qy, p.y, dt);
                    dt = __fmaf_rn(qz, p.z, dt);
                    const float d2 = __fsub_rn(__fadd_rn(sq, sp),
                                               __fmul_rn(2.0f, dt));
                    in = d2 < R2;
                    pidx = __float_as_int(p.w);
                }
                const unsigned mask = __ballot_sync(0xffffffffu, in);
                if (in) {
                    const int pos = cnt + __popc(mask & lt_mask);
                    if (pos < HCAP) hlist[warp][pos] = pidx;
                }
                cnt += __popc(mask);
            }
        }
    }
    if (cnt > HCAP) cnt = HCAP;

    int v0 = (lane < cnt)      ? hlist[warp][lane]      : INT_MAX;
    int v1 = (32 + lane < cnt) ? hlist[warp][32 + lane] : INT_MAX;
    if (cnt <= 64) {
        bitonic64(v0, v1, lane);
    } else {
        int v2 = (64 + lane < cnt) ? hlist[warp][64 + lane] : INT_MAX;
        int v3 = (96 + lane < cnt) ? hlist[warp][96 + lane] : INT_MAX;
        bitonic128(v0, v1, v2, v3, lane);
    }

    const int f0 = __shfl_sync(0xffffffffu, v0, 0);
    const int first = (cnt == 0) ? 0 : f0;
    g_idx[q * 64 + lane]      = (lane < cnt)      ? v0 : first;
    g_idx[q * 64 + 32 + lane] = (32 + lane < cnt) ? v1 : first;
}

// ---------------------------------------------------------------------------
// Gather + concat (swizzled smem as in passing R6) + streaming output stores.
// ---------------------------------------------------------------------------
__global__ void __launch_bounds__(256) gather_kernel(
    const float* __restrict__ new_xyz, float* __restrict__ out)
{
    __shared__ int   sidx[64];
    __shared__ float srow[64][ROWF];
    const int b   = blockIdx.y;
    const int m   = blockIdx.x;
    const int tid = threadIdx.x;
    const int q   = b * MM + m;

    if (tid < 64) sidx[tid] = g_idx[q * 64 + tid];
    __syncthreads();

    // stage: 64 rows x 17 quads. LDG.128 -> swizzled STS.128 / xyz scalars.
    for (int f = tid; f < 64 * 17; f += 256) {
        const int r = f / 17;
        const int j = f - r * 17;
        float4 v = ((const float4*)(g_ptsT +
                    (size_t)(b * NN + sidx[r]) * ROWF))[j];
        if (j < 16) {
            if (r & 1) { float t = v.x; v.x = v.y; v.y = t;
                         t = v.z; v.z = v.w; v.w = t; }
            if (r & 2) { float t = v.x; v.x = v.z; v.z = t;
                         t = v.y; v.y = v.w; v.w = t; }
            const int jq = j ^ ((r >> 2) & 7);
            *((float4*)&srow[r][4 * jq]) = v;
        } else {
            srow[r][64] = v.x;
            srow[r][65] = v.y;
            srow[r][66] = v.z;
        }
    }
    __syncthreads();

    // output: tasks (c, k4h 0..7); warp spans 4 c x 8 k4h -> conflict-free LDS.
    for (int t = tid; t < 67 * 8; t += 256) {
        const int c   = t >> 3;
        const int k4h = t & 7;
        float sub = 0.0f;
        if (c < 3) sub = new_xyz[(b * 3 + c) * MM + m];
        #pragma unroll
        for (int h = 0; h < 2; ++h) {
            const int k4 = k4h + 8 * h;
            const int k  = 4 * k4;
            float4 v;
            if (c < 3) {
                v.x = srow[k + 0][64 + c] - sub;
                v.y = srow[k + 1][64 + c] - sub;
                v.z = srow[k + 2][64 + c] - sub;
                v.w = srow[k + 3][64 + c] - sub;
            } else {
                const int cf = c - 3;
                v.x = srow[k + 0][cf ^ ((k + 0) & 31)];
                v.y = srow[k + 1][cf ^ ((k + 1) & 31)];
                v.z = srow[k + 2][cf ^ ((k + 2) & 31)];
                v.w = srow[k + 3][cf ^ ((k + 3) & 31)];
            }
            __stcs(((float4*)(out + (((size_t)b * 67 + c) * MM + m) * 64)) + k4, v);
        }
    }
}

// ---------------------------------------------------------------------------
extern "C" void kernel_launch(void* const* d_in, const int* in_sizes, int n_in,
                              void* d_out, int out_size)
{
    const float* new_xyz = (const float*)d_in[0];  // (8, 3, 2048)
    const float* xyz     = (const float*)d_in[1];  // (8, 3, 8192)
    const float* feature = (const float*)d_in[2];  // (8, 64, 8192)
    float* out = (float*)d_out;                    // (8, 67, 2048, 64)

    build_and_transpose_kernel<<<8 + (NN / TPTS) * BB, 1024>>>(xyz, feature);
    ballquery_cells_kernel<<<dim3(MM / 8, BB), 256>>>(new_xyz);
    gather_kernel<<<dim3(MM, BB), 256>>>(new_xyz, out);
}

// round 8
// speedup vs baseline: 2.2720x; 1.0344x over previous
#include <cuda_runtime.h>
#include <limits.h>

#define BB 8
#define NN 8192
#define MM 2048
#define CC 64
#define KK 64
#define R2 0.01f
#define ROWF 68            // floats per row: [f0..f63, x, y, z, pad] (272B)
#define NCELL 1000         // 10x10x10 grid, cell size 0.1
#define RREACH 0.1002f     // conservative cell reach (covers d2 rounding slack)
#define HCAP 128           // per-query candidate-hit cap (max expected ~75)

// Scratch (no cudaMalloc allowed)
__device__ float  g_ptsT[BB * NN * ROWF];        // transposed point rows
__device__ int    g_idx[BB * MM * KK];           // neighbor indices
__device__ int    g_cellcnt[BB * NCELL];         // zero-init; re-zeroed by scan
__device__ int    g_cellstart[BB * (NCELL + 1)];
__device__ int    g_cellofs[BB * NCELL];
__device__ float4 g_cellpts[BB * NN];            // (x,y,z, idx-bits) cell-sorted

__device__ __forceinline__ int cell_of(float x, float y, float z)
{
    int cx = (int)(x * 10.0f); cx = min(max(cx, 0), 9);
    int cy = (int)(y * 10.0f); cy = min(max(cy, 0), 9);
    int cz = (int)(z * 10.0f); cz = min(max(cz, 0), 9);
    return (cx * 10 + cy) * 10 + cz;
}

// ---------------------------------------------------------------------------
// K1: transpose (rows [f0..f63, x, y, z, pad]) + cell histogram.
// 64 points per 256-thread block; hist via global atomics (cheap REDG).
// ---------------------------------------------------------------------------
__global__ void __launch_bounds__(256) transpose_hist_kernel(
    const float* __restrict__ xyz, const float* __restrict__ feat)
{
    __shared__ float s[64][65];      // features, padded
    __shared__ float sxyz[3][64];
    const int b   = blockIdx.y;
    const int n0  = blockIdx.x * 64;
    const int tid = threadIdx.x;
    const int p   = tid & 63;
    const int c0  = tid >> 6;

    #pragma unroll
    for (int cc = 0; cc < 64; cc += 4) {
        const int c = cc + c0;
        s[c][p] = feat[((size_t)(b * 64 + c)) * NN + n0 + p];
    }
    if (tid < 192) {
        const int c  = tid >> 6;
        const int pp = tid & 63;
        sxyz[c][pp] = xyz[((size_t)(b * 3 + c)) * NN + n0 + pp];
    }
    __syncthreads();

    // histogram: one thread per point
    if (tid < 64) {
        const int cell = cell_of(sxyz[0][tid], sxyz[1][tid], sxyz[2][tid]);
        atomicAdd(&g_cellcnt[b * NCELL + cell], 1);
    }

    // 64 rows x 17 float4 writes: quads 0..15 = features, quad 16 = xyz
    for (int f = tid; f < 64 * 17; f += 256) {
        const int pp = f / 17;
        const int j  = f - pp * 17;
        float4 v;
        if (j < 16) {
            const int c = 4 * j;
            v.x = s[c][pp]; v.y = s[c + 1][pp]; v.z = s[c + 2][pp]; v.w = s[c + 3][pp];
        } else {
            v.x = sxyz[0][pp]; v.y = sxyz[1][pp]; v.z = sxyz[2][pp]; v.w = 0.0f;
        }
        ((float4*)(g_ptsT + ((size_t)(b * NN + n0 + pp)) * ROWF))[j] = v;
    }
}

// ---------------------------------------------------------------------------
// K2: scan per batch. Reads g_cellcnt, RE-ZEROS it (replay invariant),
// writes g_cellstart and g_cellofs.
// ---------------------------------------------------------------------------
__global__ void __launch_bounds__(1024) scan_kernel()
{
    __shared__ int s[1024];
    const int b   = blockIdx.x;
    const int tid = threadIdx.x;
    const int v = (tid < NCELL) ? g_cellcnt[b * NCELL + tid] : 0;
    if (tid < NCELL) g_cellcnt[b * NCELL + tid] = 0;   // ready for next replay
    s[tid] = v;
    __syncthreads();
    #pragma unroll
    for (int d = 1; d < 1024; d <<= 1) {
        const int t = (tid >= d) ? s[tid - d] : 0;
        __syncthreads();
        s[tid] += t;
        __syncthreads();
    }
    if (tid < NCELL) {
        const int excl = s[tid] - v;
        g_cellstart[b * (NCELL + 1) + tid] = excl;
        g_cellofs[b * NCELL + tid] = excl;
    }
    if (tid == NCELL - 1)
        g_cellstart[b * (NCELL + 1) + NCELL] = s[tid];
}

// ---------------------------------------------------------------------------
// K3: scatter points into cell-sorted array (global atomics).
// ---------------------------------------------------------------------------
__global__ void __launch_bounds__(1024) scatter_kernel(const float* __restrict__ xyz)
{
    const int b = blockIdx.y;
    const int n = blockIdx.x * 1024 + threadIdx.x;
    const float x = xyz[(b * 3 + 0) * NN + n];
    const float y = xyz[(b * 3 + 1) * NN + n];
    const float z = xyz[(b * 3 + 2) * NN + n];
    const int pos = atomicAdd(&g_cellofs[b * NCELL + cell_of(x, y, z)], 1);
    g_cellpts[b * NN + pos] = make_float4(x, y, z, __int_as_float(n));
}

// ---------------------------------------------------------------------------
// Bitonic sorts (unchanged)
// ---------------------------------------------------------------------------
__device__ __forceinline__ void cmpex(int& v, int e_lane_bits, int j, int k, int lane)
{
    const int pv = __shfl_xor_sync(0xffffffffu, v, j);
    const bool up = ((e_lane_bits & k) == 0);
    const bool lo = ((lane & j) == 0);
    v = ((lo == up) ? min(v, pv) : max(v, pv));
}

__device__ __forceinline__ void bitonic64(int& v0, int& v1, int lane)
{
    #pragma unroll
    for (int k = 2; k <= 64; k <<= 1) {
        #pragma unroll
        for (int j = k >> 1; j > 0; j >>= 1) {
            if (j >= 32) {
                const int a = min(v0, v1), b2 = max(v0, v1);
                v0 = a; v1 = b2;
            } else {
                cmpex(v0, lane,      j, k, lane);
                cmpex(v1, 32 + lane, j, k, lane);
            }
        }
    }
}

__device__ __forceinline__ void bitonic128(int& v0, int& v1, int& v2, int& v3, int lane)
{
    #pragma unroll
    for (int k = 2; k <= 128; k <<= 1) {
        #pragma unroll
        for (int j = k >> 1; j > 0; j >>= 1) {
            if (j == 64) {
                int a, b2;
                a = min(v0, v2); b2 = max(v0, v2); v0 = a; v2 = b2;
                a = min(v1, v3); b2 = max(v1, v3); v1 = a; v3 = b2;
            } else if (j == 32) {
                const bool upA = (((lane)      & k) == 0);
                const bool upB = (((64 + lane) & k) == 0);
                int a, b2;
                a = min(v0, v1); b2 = max(v0, v1);
                v0 = upA ? a : b2;  v1 = upA ? b2 : a;
                a = min(v2, v3); b2 = max(v2, v3);
                v2 = upB ? a : b2;  v3 = upB ? b2 : a;
            } else {
                cmpex(v0, lane,      j, k, lane);
                cmpex(v1, 32 + lane, j, k, lane);
                cmpex(v2, 64 + lane, j, k, lane);
                cmpex(v3, 96 + lane, j, k, lane);
            }
        }
    }
}

// ---------------------------------------------------------------------------
// Ball query (unchanged from passing R7). d2 bit-exact vs reference.
// ---------------------------------------------------------------------------
__global__ void __launch_bounds__(256) ballquery_cells_kernel(
    const float* __restrict__ new_xyz)
{
    __shared__ int hlist[8][HCAP];
    const int b    = blockIdx.y;
    const int warp = threadIdx.x >> 5;
    const int lane = threadIdx.x & 31;
    const int m    = blockIdx.x * 8 + warp;
    const int q    = b * MM + m;

    const float qx = new_xyz[(b * 3 + 0) * MM + m];
    const float qy = new_xyz[(b * 3 + 1) * MM + m];
    const float qz = new_xyz[(b * 3 + 2) * MM + m];
    const float sq = __fadd_rn(__fadd_rn(__fmul_rn(qx, qx), __fmul_rn(qy, qy)),
                               __fmul_rn(qz, qz));

    const int xlo = max(0, (int)floorf((qx - RREACH) * 10.0f));
    const int xhi = min(9, (int)floorf((qx + RREACH) * 10.0f));
    const int ylo = max(0, (int)floorf((qy - RREACH) * 10.0f));
    const int yhi = min(9, (int)floorf((qy + RREACH) * 10.0f));
    const int zlo = max(0, (int)floorf((qz - RREACH) * 10.0f));
    const int zhi = min(9, (int)floorf((qz + RREACH) * 10.0f));

    const unsigned lt_mask = (lane == 0) ? 0u : (0xffffffffu >> (32 - lane));
    int cnt = 0;

    for (int cx = xlo; cx <= xhi; ++cx) {
        for (int cy = ylo; cy <= yhi; ++cy) {
            const int idbase = (cx * 10 + cy) * 10;
            const int s = g_cellstart[b * (NCELL + 1) + idbase + zlo];
            const int e = g_cellstart[b * (NCELL + 1) + idbase + zhi + 1];
            for (int i = s; i < e; i += 32) {
                const int j = i + lane;
                bool in = false;
                int  pidx = 0;
                if (j < e) {
                    const float4 p = g_cellpts[b * NN + j];
                    const float sp = __fadd_rn(
                        __fadd_rn(__fmul_rn(p.x, p.x), __fmul_rn(p.y, p.y)),
                        __fmul_rn(p.z, p.z));
                    float dt = __fmul_rn(qx, p.x);
                    dt = __fmaf_rn(qy, p.y, dt);
                    dt = __fmaf_rn(qz, p.z, dt);
                    const float d2 = __fsub_rn(__fadd_rn(sq, sp),
                                               __fmul_rn(2.0f, dt));
                    in = d2 < R2;
                    pidx = __float_as_int(p.w);
                }
                const unsigned mask = __ballot_sync(0xffffffffu, in);
                if (in) {
                    const int pos = cnt + __popc(mask & lt_mask);
                    if (pos < HCAP) hlist[warp][pos] = pidx;
                }
                cnt += __popc(mask);
            }
        }
    }
    if (cnt > HCAP) cnt = HCAP;

    int v0 = (lane < cnt)      ? hlist[warp][lane]      : INT_MAX;
    int v1 = (32 + lane < cnt) ? hlist[warp][32 + lane] : INT_MAX;
    if (cnt <= 64) {
        bitonic64(v0, v1, lane);
    } else {
        int v2 = (64 + lane < cnt) ? hlist[warp][64 + lane] : INT_MAX;
        int v3 = (96 + lane < cnt) ? hlist[warp][96 + lane] : INT_MAX;
        bitonic128(v0, v1, v2, v3, lane);
    }

    const int f0 = __shfl_sync(0xffffffffu, v0, 0);
    const int first = (cnt == 0) ? 0 : f0;
    g_idx[q * 64 + lane]      = (lane < cnt)      ? v0 : first;
    g_idx[q * 64 + 32 + lane] = (32 + lane < cnt) ? v1 : first;
}

// ---------------------------------------------------------------------------
// Gather + concat (unchanged from passing R7).
// ---------------------------------------------------------------------------
__global__ void __launch_bounds__(256) gather_kernel(
    const float* __restrict__ new_xyz, float* __restrict__ out)
{
    __shared__ int   sidx[64];
    __shared__ float srow[64][ROWF];
    const int b   = blockIdx.y;
    const int m   = blockIdx.x;
    const int tid = threadIdx.x;
    const int q   = b * MM + m;

    if (tid < 64) sidx[tid] = g_idx[q * 64 + tid];
    __syncthreads();

    for (int f = tid; f < 64 * 17; f += 256) {
        const int r = f / 17;
        const int j = f - r * 17;
        float4 v = ((const float4*)(g_ptsT +
                    (size_t)(b * NN + sidx[r]) * ROWF))[j];
        if (j < 16) {
            if (r & 1) { float t = v.x; v.x = v.y; v.y = t;
                         t = v.z; v.z = v.w; v.w = t; }
            if (r & 2) { float t = v.x; v.x = v.z; v.z = t;
                         t = v.y; v.y = v.w; v.w = t; }
            const int jq = j ^ ((r >> 2) & 7);
            *((float4*)&srow[r][4 * jq]) = v;
        } else {
            srow[r][64] = v.x;
            srow[r][65] = v.y;
            srow[r][66] = v.z;
        }
    }
    __syncthreads();

    for (int t = tid; t < 67 * 8; t += 256) {
        const int c   = t >> 3;
        const int k4h = t & 7;
        float sub = 0.0f;
        if (c < 3) sub = new_xyz[(b * 3 + c) * MM + m];
        #pragma unroll
        for (int h = 0; h < 2; ++h) {
            const int k4 = k4h + 8 * h;
            const int k  = 4 * k4;
            float4 v;
            if (c < 3) {
                v.x = srow[k + 0][64 + c] - sub;
                v.y = srow[k + 1][64 + c] - sub;
                v.z = srow[k + 2][64 + c] - sub;
                v.w = srow[k + 3][64 + c] - sub;
            } else {
                const int cf = c - 3;
                v.x = srow[k + 0][cf ^ ((k + 0) & 31)];
                v.y = srow[k + 1][cf ^ ((k + 1) & 31)];
                v.z = srow[k + 2][cf ^ ((k + 2) & 31)];
                v.w = srow[k + 3][cf ^ ((k + 3) & 31)];
            }
            __stcs(((float4*)(out + (((size_t)b * 67 + c) * MM + m) * 64)) + k4, v);
        }
    }
}

// ---------------------------------------------------------------------------
extern "C" void kernel_launch(void* const* d_in, const int* in_sizes, int n_in,
                              void* d_out, int out_size)
{
    const float* new_xyz = (const float*)d_in[0];  // (8, 3, 2048)
    const float* xyz     = (const float*)d_in[1];  // (8, 3, 8192)
    const float* feature = (const float*)d_in[2];  // (8, 64, 8192)
    float* out = (float*)d_out;                    // (8, 67, 2048, 64)

    transpose_hist_kernel<<<dim3(NN / 64, BB), 256>>>(xyz, feature);
    scan_kernel<<<BB, 1024>>>();
    scatter_kernel<<<dim3(NN / 1024, BB), 1024>>>(xyz);
    ballquery_cells_kernel<<<dim3(MM / 8, BB), 256>>>(new_xyz);
    gather_kernel<<<dim3(MM, BB), 256>>>(new_xyz, out);
}

// round 9
// speedup vs baseline: 2.2894x; 1.0076x over previous
#include <cuda_runtime.h>
#include <limits.h>

#define BB 8
#define NN 8192
#define MM 2048
#define CC 64
#define KK 64
#define R2 0.01f
#define ROWF 68            // floats per row: [f0..f63, x, y, z, pad] (272B)
#define NCELL 1000         // 10x10x10 grid, cell size 0.1
#define RREACH 0.1002f     // conservative cell reach (covers d2 rounding slack)
#define HCAP 128           // per-query candidate-hit cap (max expected ~75)
#define MAXCOL 16          // max (cx,cy) columns per query (4x4)

// Scratch (no cudaMalloc allowed)
__device__ float  g_ptsT[BB * NN * ROWF];        // transposed point rows
__device__ int    g_idx[BB * MM * KK];           // neighbor indices
__device__ int    g_cellcnt[BB * NCELL];         // zero-init; re-zeroed by scan
__device__ int    g_cellstart[BB * (NCELL + 1)];
__device__ int    g_cellofs[BB * NCELL];
__device__ float4 g_cellpts[BB * NN];            // (x,y,z, idx-bits) cell-sorted

__device__ __forceinline__ int cell_of(float x, float y, float z)
{
    int cx = (int)(x * 10.0f); cx = min(max(cx, 0), 9);
    int cy = (int)(y * 10.0f); cy = min(max(cy, 0), 9);
    int cz = (int)(z * 10.0f); cz = min(max(cz, 0), 9);
    return (cx * 10 + cy) * 10 + cz;
}

// ---------------------------------------------------------------------------
// K1: transpose (rows [f0..f63, x, y, z, pad]) + cell histogram.
// ---------------------------------------------------------------------------
__global__ void __launch_bounds__(256) transpose_hist_kernel(
    const float* __restrict__ xyz, const float* __restrict__ feat)
{
    __shared__ float s[64][65];
    __shared__ float sxyz[3][64];
    const int b   = blockIdx.y;
    const int n0  = blockIdx.x * 64;
    const int tid = threadIdx.x;
    const int p   = tid & 63;
    const int c0  = tid >> 6;

    #pragma unroll
    for (int cc = 0; cc < 64; cc += 4) {
        const int c = cc + c0;
        s[c][p] = feat[((size_t)(b * 64 + c)) * NN + n0 + p];
    }
    if (tid < 192) {
        const int c  = tid >> 6;
        const int pp = tid & 63;
        sxyz[c][pp] = xyz[((size_t)(b * 3 + c)) * NN + n0 + pp];
    }
    __syncthreads();

    if (tid < 64) {
        const int cell = cell_of(sxyz[0][tid], sxyz[1][tid], sxyz[2][tid]);
        atomicAdd(&g_cellcnt[b * NCELL + cell], 1);
    }

    for (int f = tid; f < 64 * 17; f += 256) {
        const int pp = f / 17;
        const int j  = f - pp * 17;
        float4 v;
        if (j < 16) {
            const int c = 4 * j;
            v.x = s[c][pp]; v.y = s[c + 1][pp]; v.z = s[c + 2][pp]; v.w = s[c + 3][pp];
        } else {
            v.x = sxyz[0][pp]; v.y = sxyz[1][pp]; v.z = sxyz[2][pp]; v.w = 0.0f;
        }
        ((float4*)(g_ptsT + ((size_t)(b * NN + n0 + pp)) * ROWF))[j] = v;
    }
}

// ---------------------------------------------------------------------------
// K2: scan per batch (re-zeros g_cellcnt for replay invariance).
// ---------------------------------------------------------------------------
__global__ void __launch_bounds__(1024) scan_kernel()
{
    __shared__ int s[1024];
    const int b   = blockIdx.x;
    const int tid = threadIdx.x;
    const int v = (tid < NCELL) ? g_cellcnt[b * NCELL + tid] : 0;
    if (tid < NCELL) g_cellcnt[b * NCELL + tid] = 0;
    s[tid] = v;
    __syncthreads();
    #pragma unroll
    for (int d = 1; d < 1024; d <<= 1) {
        const int t = (tid >= d) ? s[tid - d] : 0;
        __syncthreads();
        s[tid] += t;
        __syncthreads();
    }
    if (tid < NCELL) {
        const int excl = s[tid] - v;
        g_cellstart[b * (NCELL + 1) + tid] = excl;
        g_cellofs[b * NCELL + tid] = excl;
    }
    if (tid == NCELL - 1)
        g_cellstart[b * (NCELL + 1) + NCELL] = s[tid];
}

// ---------------------------------------------------------------------------
// K3: scatter points into cell-sorted array.
// ---------------------------------------------------------------------------
__global__ void __launch_bounds__(1024) scatter_kernel(const float* __restrict__ xyz)
{
    const int b = blockIdx.y;
    const int n = blockIdx.x * 1024 + threadIdx.x;
    const float x = xyz[(b * 3 + 0) * NN + n];
    const float y = xyz[(b * 3 + 1) * NN + n];
    const float z = xyz[(b * 3 + 2) * NN + n];
    const int pos = atomicAdd(&g_cellofs[b * NCELL + cell_of(x, y, z)], 1);
    g_cellpts[b * NN + pos] = make_float4(x, y, z, __int_as_float(n));
}

// ---------------------------------------------------------------------------
// Bitonic sorts (unchanged)
// ---------------------------------------------------------------------------
__device__ __forceinline__ void cmpex(int& v, int e_lane_bits, int j, int k, int lane)
{
    const int pv = __shfl_xor_sync(0xffffffffu, v, j);
    const bool up = ((e_lane_bits & k) == 0);
    const bool lo = ((lane & j) == 0);
    v = ((lo == up) ? min(v, pv) : max(v, pv));
}

__device__ __forceinline__ void bitonic64(int& v0, int& v1, int lane)
{
    #pragma unroll
    for (int k = 2; k <= 64; k <<= 1) {
        #pragma unroll
        for (int j = k >> 1; j > 0; j >>= 1) {
            if (j >= 32) {
                const int a = min(v0, v1), b2 = max(v0, v1);
                v0 = a; v1 = b2;
            } else {
                cmpex(v0, lane,      j, k, lane);
                cmpex(v1, 32 + lane, j, k, lane);
            }
        }
    }
}

__device__ __forceinline__ void bitonic128(int& v0, int& v1, int& v2, int& v3, int lane)
{
    #pragma unroll
    for (int k = 2; k <= 128; k <<= 1) {
        #pragma unroll
        for (int j = k >> 1; j > 0; j >>= 1) {
            if (j == 64) {
                int a, b2;
                a = min(v0, v2); b2 = max(v0, v2); v0 = a; v2 = b2;
                a = min(v1, v3); b2 = max(v1, v3); v1 = a; v3 = b2;
            } else if (j == 32) {
                const bool upA = (((lane)      & k) == 0);
                const bool upB = (((64 + lane) & k) == 0);
                int a, b2;
                a = min(v0, v1); b2 = max(v0, v1);
                v0 = upA ? a : b2;  v1 = upA ? b2 : a;
                a = min(v2, v3); b2 = max(v2, v3);
                v2 = upB ? a : b2;  v3 = upB ? b2 : a;
            } else {
                cmpex(v0, lane,      j, k, lane);
                cmpex(v1, 32 + lane, j, k, lane);
                cmpex(v2, 64 + lane, j, k, lane);
                cmpex(v3, 96 + lane, j, k, lane);
            }
        }
    }
}

// ---------------------------------------------------------------------------
// Ball query: flattened candidate stream. Same candidate SET and order as the
// per-column version (columns (cx,cy) row-major, z ascending within column).
// d2 predicate byte-identical (bit-exact vs reference). Hits sorted ascending.
// ---------------------------------------------------------------------------
__global__ void __launch_bounds__(256) ballquery_cells_kernel(
    const float* __restrict__ new_xyz)
{
    __shared__ int hlist[8][HCAP];
    __shared__ int sstart[8][MAXCOL];      // span starts (cell-sorted positions)
    __shared__ int soff[8][MAXCOL + 1];    // exclusive offsets in flat stream
    const int b    = blockIdx.y;
    const int warp = threadIdx.x >> 5;
    const int lane = threadIdx.x & 31;
    const int m    = blockIdx.x * 8 + warp;
    const int q    = b * MM + m;

    const float qx = new_xyz[(b * 3 + 0) * MM + m];
    const float qy = new_xyz[(b * 3 + 1) * MM + m];
    const float qz = new_xyz[(b * 3 + 2) * MM + m];
    const float sq = __fadd_rn(__fadd_rn(__fmul_rn(qx, qx), __fmul_rn(qy, qy)),
                               __fmul_rn(qz, qz));

    const int xlo = max(0, (int)floorf((qx - RREACH) * 10.0f));
    const int xhi = min(9, (int)floorf((qx + RREACH) * 10.0f));
    const int ylo = max(0, (int)floorf((qy - RREACH) * 10.0f));
    const int yhi = min(9, (int)floorf((qy + RREACH) * 10.0f));
    const int zlo = max(0, (int)floorf((qz - RREACH) * 10.0f));
    const int zhi = min(9, (int)floorf((qz + RREACH) * 10.0f));

    const int ynum = yhi - ylo + 1;
    const int ncol = (xhi - xlo + 1) * ynum;

    // lane-parallel span fetch (same column enumeration as before)
    int sc = 0, len = 0;
    if (lane < ncol) {
        const int cx = xlo + lane / ynum;
        const int cy = ylo + (lane - (lane / ynum) * ynum);
        const int base = b * (NCELL + 1) + (cx * 10 + cy) * 10;
        sc  = g_cellstart[base + zlo];
        len = g_cellstart[base + zhi + 1] - sc;
    }
    // warp exclusive scan of len
    int inc = len;
    #pragma unroll
    for (int d = 1; d < 32; d <<= 1) {
        const int t = __shfl_up_sync(0xffffffffu, inc, d);
        if (lane >= d) inc += t;
    }
    const int total = __shfl_sync(0xffffffffu, inc, 31);
    if (lane < ncol) {
        sstart[warp][lane] = sc;
        soff[warp][lane]   = inc - len;
    }
    if (lane == 0) soff[warp][ncol] = total;
    __syncwarp();

    const unsigned lt_mask = (lane == 0) ? 0u : (0xffffffffu >> (32 - lane));
    int cnt = 0;
    int cur = 0;   // per-lane column cursor (monotone)

    for (int p0 = 0; p0 < total; p0 += 32) {
        const int pos = p0 + lane;
        const bool valid = pos < total;
        bool in = false;
        int  pidx = 0;
        if (valid) {
            while (pos >= soff[warp][cur + 1]) ++cur;   // amortized O(ncol)
            const int src = sstart[warp][cur] + (pos - soff[warp][cur]);
            const float4 p = g_cellpts[b * NN + src];
            const float sp = __fadd_rn(
                __fadd_rn(__fmul_rn(p.x, p.x), __fmul_rn(p.y, p.y)),
                __fmul_rn(p.z, p.z));
            float dt = __fmul_rn(qx, p.x);
            dt = __fmaf_rn(qy, p.y, dt);
            dt = __fmaf_rn(qz, p.z, dt);
            const float d2 = __fsub_rn(__fadd_rn(sq, sp), __fmul_rn(2.0f, dt));
            in = d2 < R2;
            pidx = __float_as_int(p.w);
        }
        const unsigned mask = __ballot_sync(0xffffffffu, in);
        if (in) {
            const int posw = cnt + __popc(mask & lt_mask);
            if (posw < HCAP) hlist[warp][posw] = pidx;
        }
        cnt += __popc(mask);
    }
    if (cnt > HCAP) cnt = HCAP;

    int v0 = (lane < cnt)      ? hlist[warp][lane]      : INT_MAX;
    int v1 = (32 + lane < cnt) ? hlist[warp][32 + lane] : INT_MAX;
    if (cnt <= 64) {
        bitonic64(v0, v1, lane);
    } else {
        int v2 = (64 + lane < cnt) ? hlist[warp][64 + lane] : INT_MAX;
        int v3 = (96 + lane < cnt) ? hlist[warp][96 + lane] : INT_MAX;
        bitonic128(v0, v1, v2, v3, lane);
    }

    const int f0 = __shfl_sync(0xffffffffu, v0, 0);
    const int first = (cnt == 0) ? 0 : f0;
    g_idx[q * 64 + lane]      = (lane < cnt)      ? v0 : first;
    g_idx[q * 64 + 32 + lane] = (32 + lane < cnt) ? v1 : first;
}

// ---------------------------------------------------------------------------
// Gather + concat (unchanged from passing R8).
// ---------------------------------------------------------------------------
__global__ void __launch_bounds__(256) gather_kernel(
    const float* __restrict__ new_xyz, float* __restrict__ out)
{
    __shared__ int   sidx[64];
    __shared__ float srow[64][ROWF];
    const int b   = blockIdx.y;
    const int m   = blockIdx.x;
    const int tid = threadIdx.x;
    const int q   = b * MM + m;

    if (tid < 64) sidx[tid] = g_idx[q * 64 + tid];
    __syncthreads();

    for (int f = tid; f < 64 * 17; f += 256) {
        const int r = f / 17;
        const int j = f - r * 17;
        float4 v = ((const float4*)(g_ptsT +
                    (size_t)(b * NN + sidx[r]) * ROWF))[j];
        if (j < 16) {
            if (r & 1) { float t = v.x; v.x = v.y; v.y = t;
                         t = v.z; v.z = v.w; v.w = t; }
            if (r & 2) { float t = v.x; v.x = v.z; v.z = t;
                         t = v.y; v.y = v.w; v.w = t; }
            const int jq = j ^ ((r >> 2) & 7);
            *((float4*)&srow[r][4 * jq]) = v;
        } else {
            srow[r][64] = v.x;
            srow[r][65] = v.y;
            srow[r][66] = v.z;
        }
    }
    __syncthreads();

    for (int t = tid; t < 67 * 8; t += 256) {
        const int c   = t >> 3;
        const int k4h = t & 7;
        float sub = 0.0f;
        if (c < 3) sub = new_xyz[(b * 3 + c) * MM + m];
        #pragma unroll
        for (int h = 0; h < 2; ++h) {
            const int k4 = k4h + 8 * h;
            const int k  = 4 * k4;
            float4 v;
            if (c < 3) {
                v.x = srow[k + 0][64 + c] - sub;
                v.y = srow[k + 1][64 + c] - sub;
                v.z = srow[k + 2][64 + c] - sub;
                v.w = srow[k + 3][64 + c] - sub;
            } else {
                const int cf = c - 3;
                v.x = srow[k + 0][cf ^ ((k + 0) & 31)];
                v.y = srow[k + 1][cf ^ ((k + 1) & 31)];
                v.z = srow[k + 2][cf ^ ((k + 2) & 31)];
                v.w = srow[k + 3][cf ^ ((k + 3) & 31)];
            }
            __stcs(((float4*)(out + (((size_t)b * 67 + c) * MM + m) * 64)) + k4, v);
        }
    }
}

// ---------------------------------------------------------------------------
extern "C" void kernel_launch(void* const* d_in, const int* in_sizes, int n_in,
                              void* d_out, int out_size)
{
    const float* new_xyz = (const float*)d_in[0];  // (8, 3, 2048)
    const float* xyz     = (const float*)d_in[1];  // (8, 3, 8192)
    const float* feature = (const float*)d_in[2];  // (8, 64, 8192)
    float* out = (float*)d_out;                    // (8, 67, 2048, 64)

    transpose_hist_kernel<<<dim3(NN / 64, BB), 256>>>(xyz, feature);
    scan_kernel<<<BB, 1024>>>();
    scatter_kernel<<<dim3(NN / 1024, BB), 1024>>>(xyz);
    ballquery_cells_kernel<<<dim3(MM / 8, BB), 256>>>(new_xyz);
    gather_kernel<<<dim3(MM, BB), 256>>>(new_xyz, out);
}

// round 10
// speedup vs baseline: 2.3323x; 1.0187x over previous
#include <cuda_runtime.h>
#include <limits.h>

#define BB 8
#define NN 8192
#define MM 2048
#define CC 64
#define KK 64
#define R2 0.01f
#define ROWF 68            // floats per row: [f0..f63, x, y, z, pad] (272B)
#define NCELL 1000         // 10x10x10 grid, cell size 0.1
#define RREACH 0.1002f     // conservative cell reach (covers d2 rounding slack)
#define HCAP 128           // per-query candidate-hit cap (max expected ~75)
#define MAXCOL 16          // max (cx,cy) columns per query (4x4)
#define NBQBLK ((MM / 8) * BB)     // 2048 ballquery blocks
#define NTRBLK ((NN / 64) * BB)    // 1024 transpose blocks

// Scratch (no cudaMalloc allowed)
__device__ float  g_ptsT[BB * NN * ROWF];        // transposed point rows
__device__ int    g_idx[BB * MM * KK];           // neighbor indices
__device__ int    g_cellcnt[BB * NCELL];         // zero-init; re-zeroed by scan
__device__ int    g_cellstart[BB * (NCELL + 1)];
__device__ int    g_cellofs[BB * NCELL];
__device__ float4 g_cellpts[BB * NN];            // (x,y,z, idx-bits) cell-sorted

__device__ __forceinline__ int cell_of(float x, float y, float z)
{
    int cx = (int)(x * 10.0f); cx = min(max(cx, 0), 9);
    int cy = (int)(y * 10.0f); cy = min(max(cy, 0), 9);
    int cz = (int)(z * 10.0f); cz = min(max(cz, 0), 9);
    return (cx * 10 + cy) * 10 + cz;
}

// ---------------------------------------------------------------------------
// K1: standalone cell histogram (coalesced loads + cheap REDG atomics).
// ---------------------------------------------------------------------------
__global__ void __launch_bounds__(256) hist_kernel(const float* __restrict__ xyz)
{
    const int b = blockIdx.y;
    const int n = blockIdx.x * 256 + threadIdx.x;
    const float x = xyz[(b * 3 + 0) * NN + n];
    const float y = xyz[(b * 3 + 1) * NN + n];
    const float z = xyz[(b * 3 + 2) * NN + n];
    atomicAdd(&g_cellcnt[b * NCELL + cell_of(x, y, z)], 1);
}

// ---------------------------------------------------------------------------
// K2: scan per batch (re-zeros g_cellcnt for replay invariance).
// ---------------------------------------------------------------------------
__global__ void __launch_bounds__(1024) scan_kernel()
{
    __shared__ int s[1024];
    const int b   = blockIdx.x;
    const int tid = threadIdx.x;
    const int v = (tid < NCELL) ? g_cellcnt[b * NCELL + tid] : 0;
    if (tid < NCELL) g_cellcnt[b * NCELL + tid] = 0;
    s[tid] = v;
    __syncthreads();
    #pragma unroll
    for (int d = 1; d < 1024; d <<= 1) {
        const int t = (tid >= d) ? s[tid - d] : 0;
        __syncthreads();
        s[tid] += t;
        __syncthreads();
    }
    if (tid < NCELL) {
        const int excl = s[tid] - v;
        g_cellstart[b * (NCELL + 1) + tid] = excl;
        g_cellofs[b * NCELL + tid] = excl;
    }
    if (tid == NCELL - 1)
        g_cellstart[b * (NCELL + 1) + NCELL] = s[tid];
}

// ---------------------------------------------------------------------------
// K3: scatter points into cell-sorted array.
// ---------------------------------------------------------------------------
__global__ void __launch_bounds__(1024) scatter_kernel(const float* __restrict__ xyz)
{
    const int b = blockIdx.y;
    const int n = blockIdx.x * 1024 + threadIdx.x;
    const float x = xyz[(b * 3 + 0) * NN + n];
    const float y = xyz[(b * 3 + 1) * NN + n];
    const float z = xyz[(b * 3 + 2) * NN + n];
    const int pos = atomicAdd(&g_cellofs[b * NCELL + cell_of(x, y, z)], 1);
    g_cellpts[b * NN + pos] = make_float4(x, y, z, __int_as_float(n));
}

// ---------------------------------------------------------------------------
// Bitonic sorts (unchanged)
// ---------------------------------------------------------------------------
__device__ __forceinline__ void cmpex(int& v, int e_lane_bits, int j, int k, int lane)
{
    const int pv = __shfl_xor_sync(0xffffffffu, v, j);
    const bool up = ((e_lane_bits & k) == 0);
    const bool lo = ((lane & j) == 0);
    v = ((lo == up) ? min(v, pv) : max(v, pv));
}

__device__ __forceinline__ void bitonic64(int& v0, int& v1, int lane)
{
    #pragma unroll
    for (int k = 2; k <= 64; k <<= 1) {
        #pragma unroll
        for (int j = k >> 1; j > 0; j >>= 1) {
            if (j >= 32) {
                const int a = min(v0, v1), b2 = max(v0, v1);
                v0 = a; v1 = b2;
            } else {
                cmpex(v0, lane,      j, k, lane);
                cmpex(v1, 32 + lane, j, k, lane);
            }
        }
    }
}

__device__ __forceinline__ void bitonic128(int& v0, int& v1, int& v2, int& v3, int lane)
{
    #pragma unroll
    for (int k = 2; k <= 128; k <<= 1) {
        #pragma unroll
        for (int j = k >> 1; j > 0; j >>= 1) {
            if (j == 64) {
                int a, b2;
                a = min(v0, v2); b2 = max(v0, v2); v0 = a; v2 = b2;
                a = min(v1, v3); b2 = max(v1, v3); v1 = a; v3 = b2;
            } else if (j == 32) {
                const bool upA = (((lane)      & k) == 0);
                const bool upB = (((64 + lane) & k) == 0);
                int a, b2;
                a = min(v0, v1); b2 = max(v0, v1);
                v0 = upA ? a : b2;  v1 = upA ? b2 : a;
                a = min(v2, v3); b2 = max(v2, v3);
                v2 = upB ? a : b2;  v3 = upB ? b2 : a;
            } else {
                cmpex(v0, lane,      j, k, lane);
                cmpex(v1, 32 + lane, j, k, lane);
                cmpex(v2, 64 + lane, j, k, lane);
                cmpex(v3, 96 + lane, j, k, lane);
            }
        }
    }
}

// ---------------------------------------------------------------------------
// K4: FUSED ballquery (blocks 0..NBQBLK-1) + transpose (rest).
// Ballquery logic byte-identical to passing R9 (d2 bit-exact vs reference);
// transpose logic byte-identical to passing R8/R9. Complementary pipes:
// ballquery = issue-bound, transpose = DRAM-bound -> overlap in one wave.
// ---------------------------------------------------------------------------
union SmemK4 {
    struct { float s[64][65]; float sxyz[3][64]; } t;
    struct { int hlist[8][HCAP]; int sstart[8][MAXCOL]; int soff[8][MAXCOL + 1]; } q;
};

__global__ void __launch_bounds__(256) fused_bq_transpose_kernel(
    const float* __restrict__ xyz, const float* __restrict__ feat,
    const float* __restrict__ new_xyz)
{
    __shared__ SmemK4 sm;
    const int tid = threadIdx.x;

    if (blockIdx.x < NBQBLK) {
        // ================= ball query =================
        const int bqid = blockIdx.x;
        const int b    = bqid >> 8;             // 256 blocks per batch
        const int warp = tid >> 5;
        const int lane = tid & 31;
        const int m    = (bqid & 255) * 8 + warp;
        const int q    = b * MM + m;

        const float qx = new_xyz[(b * 3 + 0) * MM + m];
        const float qy = new_xyz[(b * 3 + 1) * MM + m];
        const float qz = new_xyz[(b * 3 + 2) * MM + m];
        const float sq = __fadd_rn(__fadd_rn(__fmul_rn(qx, qx), __fmul_rn(qy, qy)),
                                   __fmul_rn(qz, qz));

        const int xlo = max(0, (int)floorf((qx - RREACH) * 10.0f));
        const int xhi = min(9, (int)floorf((qx + RREACH) * 10.0f));
        const int ylo = max(0, (int)floorf((qy - RREACH) * 10.0f));
        const int yhi = min(9, (int)floorf((qy + RREACH) * 10.0f));
        const int zlo = max(0, (int)floorf((qz - RREACH) * 10.0f));
        const int zhi = min(9, (int)floorf((qz + RREACH) * 10.0f));

        const int ynum = yhi - ylo + 1;
        const int ncol = (xhi - xlo + 1) * ynum;

        int sc = 0, len = 0;
        if (lane < ncol) {
            const int cx = xlo + lane / ynum;
            const int cy = ylo + (lane - (lane / ynum) * ynum);
            const int base = b * (NCELL + 1) + (cx * 10 + cy) * 10;
            sc  = g_cellstart[base + zlo];
            len = g_cellstart[base + zhi + 1] - sc;
        }
        int inc = len;
        #pragma unroll
        for (int d = 1; d < 32; d <<= 1) {
            const int t = __shfl_up_sync(0xffffffffu, inc, d);
            if (lane >= d) inc += t;
        }
        const int total = __shfl_sync(0xffffffffu, inc, 31);
        if (lane < ncol) {
            sm.q.sstart[warp][lane] = sc;
            sm.q.soff[warp][lane]   = inc - len;
        }
        if (lane == 0) sm.q.soff[warp][ncol] = total;
        __syncwarp();

        const unsigned lt_mask = (lane == 0) ? 0u : (0xffffffffu >> (32 - lane));
        int cnt = 0;
        int cur = 0;

        for (int p0 = 0; p0 < total; p0 += 32) {
            const int pos = p0 + lane;
            const bool valid = pos < total;
            bool in = false;
            int  pidx = 0;
            if (valid) {
                while (pos >= sm.q.soff[warp][cur + 1]) ++cur;
                const int src = sm.q.sstart[warp][cur] + (pos - sm.q.soff[warp][cur]);
                const float4 p = g_cellpts[b * NN + src];
                const float sp = __fadd_rn(
                    __fadd_rn(__fmul_rn(p.x, p.x), __fmul_rn(p.y, p.y)),
                    __fmul_rn(p.z, p.z));
                float dt = __fmul_rn(qx, p.x);
                dt = __fmaf_rn(qy, p.y, dt);
                dt = __fmaf_rn(qz, p.z, dt);
                const float d2 = __fsub_rn(__fadd_rn(sq, sp), __fmul_rn(2.0f, dt));
                in = d2 < R2;
                pidx = __float_as_int(p.w);
            }
            const unsigned mask = __ballot_sync(0xffffffffu, in);
            if (in) {
                const int posw = cnt + __popc(mask & lt_mask);
                if (posw < HCAP) sm.q.hlist[warp][posw] = pidx;
            }
            cnt += __popc(mask);
        }
        if (cnt > HCAP) cnt = HCAP;

        int v0 = (lane < cnt)      ? sm.q.hlist[warp][lane]      : INT_MAX;
        int v1 = (32 + lane < cnt) ? sm.q.hlist[warp][32 + lane] : INT_MAX;
        if (cnt <= 64) {
            bitonic64(v0, v1, lane);
        } else {
            int v2 = (64 + lane < cnt) ? sm.q.hlist[warp][64 + lane] : INT_MAX;
            int v3 = (96 + lane < cnt) ? sm.q.hlist[warp][96 + lane] : INT_MAX;
            bitonic128(v0, v1, v2, v3, lane);
        }

        const int f0 = __shfl_sync(0xffffffffu, v0, 0);
        const int first = (cnt == 0) ? 0 : f0;
        g_idx[q * 64 + lane]      = (lane < cnt)      ? v0 : first;
        g_idx[q * 64 + 32 + lane] = (32 + lane < cnt) ? v1 : first;
    } else {
        // ================= transpose =================
        const int t_id = blockIdx.x - NBQBLK;
        const int b    = t_id >> 7;             // 128 blocks per batch
        const int n0   = (t_id & 127) * 64;
        const int p    = tid & 63;
        const int c0   = tid >> 6;

        #pragma unroll
        for (int cc = 0; cc < 64; cc += 4) {
            const int c = cc + c0;
            sm.t.s[c][p] = feat[((size_t)(b * 64 + c)) * NN + n0 + p];
        }
        if (tid < 192) {
            const int c  = tid >> 6;
            const int pp = tid & 63;
            sm.t.sxyz[c][pp] = xyz[((size_t)(b * 3 + c)) * NN + n0 + pp];
        }
        __syncthreads();

        for (int f = tid; f < 64 * 17; f += 256) {
            const int pp = f / 17;
            const int j  = f - pp * 17;
            float4 v;
            if (j < 16) {
                const int c = 4 * j;
                v.x = sm.t.s[c][pp];     v.y = sm.t.s[c + 1][pp];
                v.z = sm.t.s[c + 2][pp]; v.w = sm.t.s[c + 3][pp];
            } else {
                v.x = sm.t.sxyz[0][pp]; v.y = sm.t.sxyz[1][pp];
                v.z = sm.t.sxyz[2][pp]; v.w = 0.0f;
            }
            ((float4*)(g_ptsT + ((size_t)(b * NN + n0 + pp)) * ROWF))[j] = v;
        }
    }
}

// ---------------------------------------------------------------------------
// Gather + concat (unchanged from passing R9).
// ---------------------------------------------------------------------------
__global__ void __launch_bounds__(256) gather_kernel(
    const float* __restrict__ new_xyz, float* __restrict__ out)
{
    __shared__ int   sidx[64];
    __shared__ float srow[64][ROWF];
    const int b   = blockIdx.y;
    const int m   = blockIdx.x;
    const int tid = threadIdx.x;
    const int q   = b * MM + m;

    if (tid < 64) sidx[tid] = g_idx[q * 64 + tid];
    __syncthreads();

    for (int f = tid; f < 64 * 17; f += 256) {
        const int r = f / 17;
        const int j = f - r * 17;
        float4 v = ((const float4*)(g_ptsT +
                    (size_t)(b * NN + sidx[r]) * ROWF))[j];
        if (j < 16) {
            if (r & 1) { float t = v.x; v.x = v.y; v.y = t;
                         t = v.z; v.z = v.w; v.w = t; }
            if (r & 2) { float t = v.x; v.x = v.z; v.z = t;
                         t = v.y; v.y = v.w; v.w = t; }
            const int jq = j ^ ((r >> 2) & 7);
            *((float4*)&srow[r][4 * jq]) = v;
        } else {
            srow[r][64] = v.x;
            srow[r][65] = v.y;
            srow[r][66] = v.z;
        }
    }
    __syncthreads();

    for (int t = tid; t < 67 * 8; t += 256) {
        const int c   = t >> 3;
        const int k4h = t & 7;
        float sub = 0.0f;
        if (c < 3) sub = new_xyz[(b * 3 + c) * MM + m];
        #pragma unroll
        for (int h = 0; h < 2; ++h) {
            const int k4 = k4h + 8 * h;
            const int k  = 4 * k4;
            float4 v;
            if (c < 3) {
                v.x = srow[k + 0][64 + c] - sub;
                v.y = srow[k + 1][64 + c] - sub;
                v.z = srow[k + 2][64 + c] - sub;
                v.w = srow[k + 3][64 + c] - sub;
            } else {
                const int cf = c - 3;
                v.x = srow[k + 0][cf ^ ((k + 0) & 31)];
                v.y = srow[k + 1][cf ^ ((k + 1) & 31)];
                v.z = srow[k + 2][cf ^ ((k + 2) & 31)];
                v.w = srow[k + 3][cf ^ ((k + 3) & 31)];
            }
            __stcs(((float4*)(out + (((size_t)b * 67 + c) * MM + m) * 64)) + k4, v);
        }
    }
}

// ---------------------------------------------------------------------------
extern "C" void kernel_launch(void* const* d_in, const int* in_sizes, int n_in,
                              void* d_out, int out_size)
{
    const float* new_xyz = (const float*)d_in[0];  // (8, 3, 2048)
    const float* xyz     = (const float*)d_in[1];  // (8, 3, 8192)
    const float* feature = (const float*)d_in[2];  // (8, 64, 8192)
    float* out = (float*)d_out;                    // (8, 67, 2048, 64)

    hist_kernel<<<dim3(NN / 256, BB), 256>>>(xyz);
    scan_kernel<<<BB, 1024>>>();
    scatter_kernel<<<dim3(NN / 1024, BB), 1024>>>(xyz);
    fused_bq_transpose_kernel<<<NBQBLK + NTRBLK, 256>>>(xyz, feature, new_xyz);
    gather_kernel<<<dim3(MM, BB), 256>>>(new_xyz, out);
}